// round 12
// baseline (speedup 1.0000x reference)
#include <cuda_runtime.h>
#include <cuda_fp16.h>
#include <stdint.h>
#include <math.h>

#define MROWS 16384   // B*T = 8*2048
#define CDIM  1024
#define HNUM  16
#define DDIM  64
#define TSEQ  2048
#define BSZ   8

// ---------------- scratch (static device memory; no runtime allocation) ----------------
__device__ float g_t1 [(size_t)MROWS * 160];
__device__ __half g_xlhi[(size_t)MROWS * CDIM], g_xllo[(size_t)MROWS * CDIM];
__device__ __half g_w0hi[(size_t)MROWS * CDIM], g_w0lo[(size_t)MROWS * CDIM];
__device__ __half g_g0hi[(size_t)MROWS * CDIM], g_g0lo[(size_t)MROWS * CDIM];
__device__ __half g_g1hi[(size_t)MROWS * 160],  g_g1lo[(size_t)MROWS * 160];
__device__ __half g_h1hi[(size_t)MROWS * 64],   g_h1lo[(size_t)MROWS * 64];
__device__ __half g_khi[(size_t)MROWS * CDIM], g_klo[(size_t)MROWS * CDIM];
__device__ __half g_vhi[(size_t)MROWS * CDIM], g_vlo[(size_t)MROWS * CDIM];
__device__ __half g_rhi[(size_t)MROWS * CDIM], g_rlo[(size_t)MROWS * CDIM];
__device__ __half g_yhi[(size_t)MROWS * CDIM], g_ylo[(size_t)MROWS * CDIM];
__device__ __half g_Whi[4][(size_t)CDIM * CDIM];
__device__ __half g_Athi[(size_t)256 * CDIM];
__device__ __half g_tdAthi[(size_t)128 * CDIM];
__device__ __half g_tdBthi[(size_t)CDIM * 64];
__device__ __half g_G1thi[(size_t)256 * CDIM];
__device__ __half g_G2thi[(size_t)CDIM * 160];
__device__ float g_w  [(size_t)MROWS * CDIM];
__device__ float g_dec[(size_t)MROWS * CDIM];
__device__ float g_kb [(size_t)MROWS * CDIM];
__device__ float g_vb [(size_t)MROWS * CDIM];
__device__ float g_rb [(size_t)MROWS * CDIM];
__device__ float g_gb [(size_t)MROWS * CDIM];
__device__ float g_yb [(size_t)MROWS * CDIM];
__device__ float g_cv [(size_t)MROWS * HNUM];

// ======================================================================================
// helpers
// ======================================================================================
__device__ __forceinline__ uint32_t smem_u32(const void* p) {
    uint32_t a;
    asm("{ .reg .u64 t; cvta.to.shared.u64 t, %1; cvt.u32.u64 %0, t; }" : "=r"(a) : "l"(p));
    return a;
}
__device__ __forceinline__ void ldsm4(uint32_t* r, uint32_t addr) {
    asm volatile("ldmatrix.sync.aligned.m8n8.x4.shared.b16 {%0,%1,%2,%3}, [%4];"
        : "=r"(r[0]), "=r"(r[1]), "=r"(r[2]), "=r"(r[3]) : "r"(addr));
}
__device__ __forceinline__ void mma16816(float* c, const uint32_t* a, const uint32_t* b) {
    asm volatile("mma.sync.aligned.m16n8k16.row.col.f32.f16.f16.f32 "
        "{%0,%1,%2,%3}, {%4,%5,%6,%7}, {%8,%9}, {%0,%1,%2,%3};"
        : "+f"(c[0]), "+f"(c[1]), "+f"(c[2]), "+f"(c[3])
        : "r"(a[0]), "r"(a[1]), "r"(a[2]), "r"(a[3]), "r"(b[0]), "r"(b[1]));
}
__device__ __forceinline__ void mma16816h(uint32_t* c, const uint32_t* a, const uint32_t* b) {
    asm volatile("mma.sync.aligned.m16n8k16.row.col.f16.f16.f16.f16 "
        "{%0,%1}, {%2,%3,%4,%5}, {%6,%7}, {%0,%1};"
        : "+r"(c[0]), "+r"(c[1])
        : "r"(a[0]), "r"(a[1]), "r"(a[2]), "r"(a[3]), "r"(b[0]), "r"(b[1]));
}
#define CP16(d, s) asm volatile("cp.async.cg.shared.global [%0], [%1], 16;" :: "r"(d), "l"(s))
#define CP4(d, s)  asm volatile("cp.async.ca.shared.global [%0], [%1], 4;"  :: "r"(d), "l"(s))
#define CPCOMMIT() asm volatile("cp.async.commit_group;" ::: "memory")
#define CPWAIT1()  asm volatile("cp.async.wait_group 1;" ::: "memory")
#define CPWAIT5()  asm volatile("cp.async.wait_group 5;" ::: "memory")

__device__ __forceinline__ void cvt_hilo4h(float4 v, uint2& hi, uint2& lo) {
    __half h0 = __float2half_rn(v.x), h1 = __float2half_rn(v.y);
    __half h2 = __float2half_rn(v.z), h3 = __float2half_rn(v.w);
    __half l0 = __float2half_rn(v.x - __half2float(h0));
    __half l1 = __float2half_rn(v.y - __half2float(h1));
    __half l2 = __float2half_rn(v.z - __half2float(h2));
    __half l3 = __float2half_rn(v.w - __half2float(h3));
    __half2 H01 = __halves2half2(h0, h1), H23 = __halves2half2(h2, h3);
    __half2 L01 = __halves2half2(l0, l1), L23 = __halves2half2(l2, l3);
    hi = make_uint2(*(uint32_t*)&H01, *(uint32_t*)&H23);
    lo = make_uint2(*(uint32_t*)&L01, *(uint32_t*)&L23);
}
__device__ __forceinline__ uint2 cvt_hi4(float4 v) {
    __half2 H01 = __halves2half2(__float2half_rn(v.x), __float2half_rn(v.y));
    __half2 H23 = __halves2half2(__float2half_rn(v.z), __float2half_rn(v.w));
    return make_uint2(*(uint32_t*)&H01, *(uint32_t*)&H23);
}

// ======================================================================================
// prep kernels
// ======================================================================================
struct SplitBatch { const float* src[4]; };

__global__ void __launch_bounds__(256) split4_kernel(
    SplitBatch sb, __half* __restrict__ hi, int n4)
{
    int idx = blockIdx.x * 256 + threadIdx.x;
    if (idx >= n4) return;
    const size_t zoff = (size_t)blockIdx.y * CDIM * CDIM;
    *(uint2*)(hi + zoff + (size_t)idx * 4) = cvt_hi4(((const float4*)sb.src[blockIdx.y])[idx]);
}

__global__ void __launch_bounds__(256) tpad_h(
    const float* __restrict__ in, __half* __restrict__ ohi, int K, int N, int Npad)
{
    int t = blockIdx.x * 256 + threadIdx.x;
    if (t >= Npad * K) return;
    int n = t / K, k = t - n * K;
    float v = (n < N) ? in[(size_t)k * N + n] : 0.f;
    ohi[t] = __float2half_rn(v);
}

__global__ void __launch_bounds__(256) xprep_kernel(
    const float4* __restrict__ x, const float4* __restrict__ xl,
    const float* __restrict__ miux,
    __half* __restrict__ xhi, __half* __restrict__ xlo,
    float4* __restrict__ xraw)
{
    int idx = blockIdx.x * 256 + threadIdx.x;   // MC/4 total
    float4 xv = x[idx], xlv = xl[idx];
    float4 mv = *(const float4*)(miux + (idx & 255) * 4);
    float4 o;
    o.x = fmaf(xlv.x - xv.x, mv.x, xv.x);
    o.y = fmaf(xlv.y - xv.y, mv.y, xv.y);
    o.z = fmaf(xlv.z - xv.z, mv.z, xv.z);
    o.w = fmaf(xlv.w - xv.w, mv.w, xv.w);
    uint2 h, l;
    cvt_hilo4h(o, h, l);
    *(uint2*)(xhi + (size_t)idx * 4) = h;
    *(uint2*)(xlo + (size_t)idx * 4) = l;
    xraw[idx] = xv;
}

// ======================================================================================
// fp16 HMMA GEMM: C[m,n] = sum_k (Ahi+Alo)[m,k] * Bhi[n,k]
// hi-pass f32-acc; lo-pass f16-acc (contribution ~2^-12 -> fp16 acc error negligible),
// merged into f32 accs per mt per k-step. Tile 128x128, BK=32, 2-stage cp.async.
// ======================================================================================
#define STG_A 30720
#define OAL3  10240
#define OBH3  20480

struct GemmSet {
    const __half *ahi, *alo, *bhi;
    float* c;
    const float* wptr;
};
struct GemmBatch { GemmSet s[3]; };

template <int EPI, int KCH>
__global__ void __launch_bounds__(256, 2) mma_gemm16(
    GemmBatch gbat, int kst, __half* __restrict__ chi, __half* __restrict__ clo)
{
    const GemmSet gs = gbat.s[blockIdx.z];
    extern __shared__ char smem[];
    const int tid = threadIdx.x, wid = tid >> 5, lane = tid & 31;
    const int bm = blockIdx.y, bn = blockIdx.x;
    const uint32_t sbase = smem_u32(smem);

    const int row = tid >> 1, half = tid & 1;
    const __half* pAhi = gs.ahi + (size_t)(bm * 128 + row) * kst + half * 16;
    const __half* pAlo = gs.alo + (size_t)(bm * 128 + row) * kst + half * 16;
    const __half* pBhi = gs.bhi + (size_t)(bn * 128 + row) * kst + half * 16;
    const uint32_t dA = (uint32_t)(row * 80 + half * 32);

    auto issue = [&](int s, int k0) {
        uint32_t sb2 = sbase + s * STG_A;
        CP16(sb2 + dA,             pAhi + k0); CP16(sb2 + dA + 16,        pAhi + k0 + 8);
        CP16(sb2 + OAL3 + dA,      pAlo + k0); CP16(sb2 + OAL3 + dA + 16, pAlo + k0 + 8);
        CP16(sb2 + OBH3 + dA,      pBhi + k0); CP16(sb2 + OBH3 + dA + 16, pBhi + k0 + 8);
    };

    float acc[2][8][4];
#pragma unroll
    for (int a = 0; a < 2; a++)
#pragma unroll
        for (int b = 0; b < 8; b++)
#pragma unroll
            for (int c = 0; c < 4; c++) acc[a][b][c] = 0.f;

    const int arow = (wid & 3) * 32 + (lane & 7) + ((lane >> 3) & 1) * 8;
    const int acol8 = (lane >> 4) * 8;
    const int brow = (wid >> 2) * 64 + ((lane >> 4) << 3) + (lane & 7);
    const int bcol8 = ((lane >> 3) & 1) * 8;

    issue(0, 0);  CPCOMMIT();
    if (KCH > 1) issue(1, 32);
    CPCOMMIT();

    for (int c = 0; c < KCH; c++) {
        CPWAIT1();
        __syncthreads();
        const uint32_t sA = sbase + (c & 1) * STG_A;
#pragma unroll
        for (int ks = 0; ks < 2; ks++) {
            const int kc = ks * 16;
            uint32_t ah[2][4], al[2][4], bh[4][4];
#pragma unroll
            for (int mt = 0; mt < 2; mt++) {
                uint32_t off = (uint32_t)((arow + mt * 16) * 40 + kc + acol8) * 2;
                ldsm4(ah[mt], sA + off);
                ldsm4(al[mt], sA + OAL3 + off);
            }
#pragma unroll
            for (int nt2 = 0; nt2 < 4; nt2++) {
                uint32_t boff = (uint32_t)((brow + nt2 * 16) * 40 + kc + bcol8) * 2;
                ldsm4(bh[nt2], sA + OBH3 + boff);
            }
            // hi-pass: f32 accumulators, 16 distinct
#pragma unroll
            for (int nt2 = 0; nt2 < 4; nt2++)
#pragma unroll
                for (int mt = 0; mt < 2; mt++) {
                    mma16816(acc[mt][nt2 * 2],     ah[mt], bh[nt2]);
                    mma16816(acc[mt][nt2 * 2 + 1], ah[mt], bh[nt2] + 2);
                }
            // lo-pass: f16 accumulators, merged per mt
#pragma unroll
            for (int mt = 0; mt < 2; mt++) {
                uint32_t accH[8][2];
#pragma unroll
                for (int q = 0; q < 8; q++) { accH[q][0] = 0u; accH[q][1] = 0u; }
#pragma unroll
                for (int nt2 = 0; nt2 < 4; nt2++) {
                    mma16816h(accH[nt2 * 2],     al[mt], bh[nt2]);
                    mma16816h(accH[nt2 * 2 + 1], al[mt], bh[nt2] + 2);
                }
#pragma unroll
                for (int nt = 0; nt < 8; nt++) {
                    float2 f0 = __half22float2(*(__half2*)&accH[nt][0]);
                    float2 f1 = __half22float2(*(__half2*)&accH[nt][1]);
                    acc[mt][nt][0] += f0.x; acc[mt][nt][1] += f0.y;
                    acc[mt][nt][2] += f1.x; acc[mt][nt][3] += f1.y;
                }
            }
        }
        __syncthreads();
        {
            int cn = c + 2;
            if (cn < KCH) issue(cn & 1, cn * 32);
            CPCOMMIT();
        }
    }

    // epilogue
#pragma unroll
    for (int mt = 0; mt < 2; mt++) {
        const int m = bm * 128 + (wid & 3) * 32 + mt * 16 + (lane >> 2);
#pragma unroll
        for (int nt = 0; nt < 8; nt++) {
            const int n = bn * 128 + (wid >> 2) * 64 + nt * 8 + (lane & 3) * 2;
            float c0 = acc[mt][nt][0], c1 = acc[mt][nt][1];
            float c2 = acc[mt][nt][2], c3 = acc[mt][nt][3];
            if (EPI == 0) {
                size_t i0 = (size_t)m * CDIM + n;
                size_t i1 = i0 + (size_t)8 * CDIM;
                if (gs.wptr) {
                    float2 wa = *(const float2*)(gs.wptr + i0);
                    float2 wb = *(const float2*)(gs.wptr + i1);
                    c0 *= __expf(fminf(wa.x, 0.f)); c1 *= __expf(fminf(wa.y, 0.f));
                    c2 *= __expf(fminf(wb.x, 0.f)); c3 *= __expf(fminf(wb.y, 0.f));
                }
                *(float2*)(gs.c + i0) = make_float2(c0, c1);
                *(float2*)(gs.c + i1) = make_float2(c2, c3);
            } else if (EPI == 4) {
                size_t i0 = (size_t)m * CDIM + n;
                size_t i1 = i0 + (size_t)8 * CDIM;
                c0 += gs.wptr[n];     c1 += gs.wptr[n + 1];
                c2 += gs.wptr[n];     c3 += gs.wptr[n + 1];
                float* dec = (float*)chi;
                *(float2*)(gs.c + i0) = make_float2(c0, c1);
                *(float2*)(gs.c + i1) = make_float2(c2, c3);
                *(float2*)(dec + i0) = make_float2(__expf(-__expf(c0)), __expf(-__expf(c1)));
                *(float2*)(dec + i1) = make_float2(__expf(-__expf(c2)), __expf(-__expf(c3)));
            } else {
                const int NS = (EPI == 5) ? 64 : 160;
                if (n >= NS) continue;
                c0 = tanhf(c0); c1 = tanhf(c1); c2 = tanhf(c2); c3 = tanhf(c3);
                size_t i0 = (size_t)m * NS + n;
                size_t i1 = i0 + (size_t)8 * NS;
                if (EPI == 2) {
                    *(float2*)(gs.c + i0) = make_float2(c0, c1);
                    *(float2*)(gs.c + i1) = make_float2(c2, c3);
                } else {
                    __half h0 = __float2half_rn(c0), h1 = __float2half_rn(c1);
                    __half h2 = __float2half_rn(c2), h3 = __float2half_rn(c3);
                    __half l0 = __float2half_rn(c0 - __half2float(h0));
                    __half l1 = __float2half_rn(c1 - __half2float(h1));
                    __half l2 = __float2half_rn(c2 - __half2float(h2));
                    __half l3 = __float2half_rn(c3 - __half2float(h3));
                    __half2 H01 = __halves2half2(h0, h1), H23 = __halves2half2(h2, h3);
                    __half2 L01 = __halves2half2(l0, l1), L23 = __halves2half2(l2, l3);
                    *(uint32_t*)(chi + i0) = *(uint32_t*)&H01;
                    *(uint32_t*)(chi + i1) = *(uint32_t*)&H23;
                    *(uint32_t*)(clo + i0) = *(uint32_t*)&L01;
                    *(uint32_t*)(clo + i1) = *(uint32_t*)&L23;
                }
            }
        }
    }
}

// ======================================================================================
// fused xdd (K=32 LoRA): all 5 outputs -> fp16 hi/lo
// ======================================================================================
__global__ void __launch_bounds__(256) xdd_fused(
    const float* __restrict__ t1, const float* __restrict__ Blo5,
    const float* __restrict__ x, const float* __restrict__ xl,
    const float* __restrict__ lam,
    __half* __restrict__ w0hi, __half* __restrict__ w0lo,
    __half* __restrict__ g0hi, __half* __restrict__ g0lo,
    __half* __restrict__ khi, __half* __restrict__ klo,
    __half* __restrict__ vhi, __half* __restrict__ vlo,
    __half* __restrict__ rhi, __half* __restrict__ rlo)
{
    extern __shared__ float sh[];
    float* T1 = sh;              // [5][64][32]
    float* BL = sh + 10240;      // [5][32][64]
    const int tid = threadIdx.x;
    const int bm = blockIdx.y, bn = blockIdx.x;
    const int tx = tid & 15, ty = tid >> 4;

#pragma unroll
    for (int ii = 0; ii < 10; ii++) {
        int c4 = tid + ii * 256;
        int f = c4 >> 9, rem = c4 & 511;
        int row = rem >> 3, kq = rem & 7;
        float4 v = *(const float4*)(t1 + (size_t)f * MROWS * 32 + (size_t)(bm * 64 + row) * 32 + kq * 4);
        *(float4*)&T1[(f * 64 + row) * 32 + kq * 4] = v;
    }
#pragma unroll
    for (int ii = 0; ii < 10; ii++) {
        int c4 = tid + ii * 256;
        int f = c4 >> 9, rem = c4 & 511;
        int k = rem >> 4, cq = rem & 15;
        float4 v = *(const float4*)(Blo5 + (size_t)f * 32 * CDIM + (size_t)k * CDIM + bn * 64 + cq * 4);
        *(float4*)&BL[(f * 32 + k) * 64 + cq * 4] = v;
    }
    __syncthreads();

    float acc[5][4][4];
#pragma unroll
    for (int f = 0; f < 5; f++)
#pragma unroll
        for (int i = 0; i < 4; i++)
#pragma unroll
            for (int j = 0; j < 4; j++) acc[f][i][j] = 0.f;

    for (int k = 0; k < 32; k++) {
#pragma unroll
        for (int f = 0; f < 5; f++) {
            float4 b = *(const float4*)&BL[(f * 32 + k) * 64 + tx * 4];
            float a0 = T1[(f * 64 + ty * 4 + 0) * 32 + k];
            float a1 = T1[(f * 64 + ty * 4 + 1) * 32 + k];
            float a2 = T1[(f * 64 + ty * 4 + 2) * 32 + k];
            float a3 = T1[(f * 64 + ty * 4 + 3) * 32 + k];
            acc[f][0][0] = fmaf(a0, b.x, acc[f][0][0]); acc[f][0][1] = fmaf(a0, b.y, acc[f][0][1]);
            acc[f][0][2] = fmaf(a0, b.z, acc[f][0][2]); acc[f][0][3] = fmaf(a0, b.w, acc[f][0][3]);
            acc[f][1][0] = fmaf(a1, b.x, acc[f][1][0]); acc[f][1][1] = fmaf(a1, b.y, acc[f][1][1]);
            acc[f][1][2] = fmaf(a1, b.z, acc[f][1][2]); acc[f][1][3] = fmaf(a1, b.w, acc[f][1][3]);
            acc[f][2][0] = fmaf(a2, b.x, acc[f][2][0]); acc[f][2][1] = fmaf(a2, b.y, acc[f][2][1]);
            acc[f][2][2] = fmaf(a2, b.z, acc[f][2][2]); acc[f][2][3] = fmaf(a2, b.w, acc[f][2][3]);
            acc[f][3][0] = fmaf(a3, b.x, acc[f][3][0]); acc[f][3][1] = fmaf(a3, b.y, acc[f][3][1]);
            acc[f][3][2] = fmaf(a3, b.z, acc[f][3][2]); acc[f][3][3] = fmaf(a3, b.w, acc[f][3][3]);
        }
    }

    const int n0 = bn * 64 + tx * 4;
    float4 lamv[5];
#pragma unroll
    for (int f = 0; f < 5; f++) lamv[f] = *(const float4*)(lam + f * CDIM + n0);

#pragma unroll
    for (int i = 0; i < 4; i++) {
        const int m = bm * 64 + ty * 4 + i;
        size_t ix = (size_t)m * CDIM + n0;
        float4 xv = *(const float4*)(x + ix);
        float4 xlv = *(const float4*)(xl + ix);
        float4 ba = make_float4(xlv.x - xv.x, xlv.y - xv.y, xlv.z - xv.z, xlv.w - xv.w);
        float4 o[5];
#pragma unroll
        for (int f = 0; f < 5; f++) {
            o[f].x = fmaf(ba.x, lamv[f].x + acc[f][i][0], xv.x);
            o[f].y = fmaf(ba.y, lamv[f].y + acc[f][i][1], xv.y);
            o[f].z = fmaf(ba.z, lamv[f].z + acc[f][i][2], xv.z);
            o[f].w = fmaf(ba.w, lamv[f].w + acc[f][i][3], xv.w);
        }
        uint2 h, l;
        cvt_hilo4h(o[0], h, l); *(uint2*)(w0hi + ix) = h; *(uint2*)(w0lo + ix) = l;
        cvt_hilo4h(o[1], h, l); *(uint2*)(khi + ix) = h; *(uint2*)(klo + ix) = l;
        cvt_hilo4h(o[2], h, l); *(uint2*)(vhi + ix) = h; *(uint2*)(vlo + ix) = l;
        cvt_hilo4h(o[3], h, l); *(uint2*)(rhi + ix) = h; *(uint2*)(rlo + ix) = l;
        cvt_hilo4h(o[4], h, l); *(uint2*)(g0hi + ix) = h; *(uint2*)(g0lo + ix) = l;
    }
}

// ======================================================================================
// cvec[m,h] = sum_j r*u*k
// ======================================================================================
__global__ void __launch_bounds__(256) cvec_kernel(
    const float* __restrict__ rb, const float* __restrict__ kb,
    const float* __restrict__ u, float* __restrict__ cv)
{
    int gw = (blockIdx.x * 256 + threadIdx.x) >> 5;
    int lane = threadIdx.x & 31;
    int m = gw >> 4, h = gw & 15;
    size_t base = (size_t)m * CDIM + h * DDIM;
    float p = rb[base + lane] * u[h * DDIM + lane] * kb[base + lane]
            + rb[base + 32 + lane] * u[h * DDIM + 32 + lane] * kb[base + 32 + lane];
#pragma unroll
    for (int o = 16; o > 0; o >>= 1) p += __shfl_xor_sync(0xffffffffu, p, o);
    if (lane == 0) cv[(size_t)m * HNUM + h] = p;
}

// ======================================================================================
// WKV-6 scan — 256 threads, PF=16 cp.async ring, TWO steps per barrier
// ======================================================================================
#define PF 16
__global__ void __launch_bounds__(256) wkv_kernel(
    const float* __restrict__ r, const float* __restrict__ k,
    const float* __restrict__ v, const float* __restrict__ dec,
    const float* __restrict__ cv, const float* __restrict__ s_in,
    float* __restrict__ y, float* __restrict__ s_out)
{
    const int bh = blockIdx.x;
    const int b = bh >> 4, h = bh & 15;
    const int tid = threadIdx.x;
    const int i  = tid & 63;
    const int jg = tid >> 6;
    const int j0 = jg * 16;

    __shared__ float buf[PF][4][64];
    __shared__ float cb[PF];
    __shared__ float ypart[2][2][4][64];

    float st[16];
    size_t sbase = (((size_t)b * HNUM + h) * DDIM + j0) * DDIM + i;
#pragma unroll
    for (int q = 0; q < 16; q++) st[q] = s_in[sbase + (size_t)q * DDIM];

    const int arr = tid >> 6, idx = tid & 63;
    const float* lp = (arr == 0) ? r : (arr == 1) ? k : (arr == 2) ? v : dec;
    const size_t base0 = ((size_t)b * TSEQ) * CDIM + h * DDIM;
    const size_t cvbase = (size_t)(b * TSEQ) * HNUM + h;

    const uint32_t sbuf = smem_u32(&buf[0][0][0]);
    const uint32_t scb  = smem_u32(&cb[0]);
    const uint32_t mydst = (uint32_t)((arr * 64 + idx) * 4);

    // prologue: 7 groups, each covering 2 steps (0..13)
    for (int p = 0; p < 7; p++) {
        CP4(sbuf + (uint32_t)((2 * p) * 1024) + mydst,     lp + base0 + (size_t)(2 * p) * CDIM + idx);
        CP4(sbuf + (uint32_t)((2 * p + 1) * 1024) + mydst, lp + base0 + (size_t)(2 * p + 1) * CDIM + idx);
        if (tid == 0) {
            CP4(scb + (2 * p) * 4,     cv + cvbase + (size_t)(2 * p) * HNUM);
            CP4(scb + (2 * p + 1) * 4, cv + cvbase + (size_t)(2 * p + 1) * HNUM);
        }
        CPCOMMIT();
    }
    CPWAIT5();          // steps 0..3 ready
    __syncthreads();

    for (int t = 0; t < TSEQ; t += 2) {
        const int it = (t >> 1) & 1;
        const int sl0 = t & (PF - 1), sl1 = (t + 1) & (PF - 1);

        // step A
        {
            const float vi = buf[sl0][2][i];
            float acc = 0.f;
#pragma unroll
            for (int q = 0; q < 16; q += 4) {
                float4 r4 = *(const float4*)&buf[sl0][0][j0 + q];
                float4 k4 = *(const float4*)&buf[sl0][1][j0 + q];
                float4 d4 = *(const float4*)&buf[sl0][3][j0 + q];
                acc = fmaf(r4.x, st[q + 0], acc); st[q + 0] = fmaf(d4.x, st[q + 0], k4.x * vi);
                acc = fmaf(r4.y, st[q + 1], acc); st[q + 1] = fmaf(d4.y, st[q + 1], k4.y * vi);
                acc = fmaf(r4.z, st[q + 2], acc); st[q + 2] = fmaf(d4.z, st[q + 2], k4.z * vi);
                acc = fmaf(r4.w, st[q + 3], acc); st[q + 3] = fmaf(d4.w, st[q + 3], k4.w * vi);
            }
            ypart[it][0][jg][i] = acc;
        }
        // step B
        {
            const float vi = buf[sl1][2][i];
            float acc = 0.f;
#pragma unroll
            for (int q = 0; q < 16; q += 4) {
                float4 r4 = *(const float4*)&buf[sl1][0][j0 + q];
                float4 k4 = *(const float4*)&buf[sl1][1][j0 + q];
                float4 d4 = *(const float4*)&buf[sl1][3][j0 + q];
                acc = fmaf(r4.x, st[q + 0], acc); st[q + 0] = fmaf(d4.x, st[q + 0], k4.x * vi);
                acc = fmaf(r4.y, st[q + 1], acc); st[q + 1] = fmaf(d4.y, st[q + 1], k4.y * vi);
                acc = fmaf(r4.z, st[q + 2], acc); st[q + 2] = fmaf(d4.z, st[q + 2], k4.z * vi);
                acc = fmaf(r4.w, st[q + 3], acc); st[q + 3] = fmaf(d4.w, st[q + 3], k4.w * vi);
            }
            ypart[it][1][jg][i] = acc;
        }

        float vA = 0.f, cA = 0.f, vB = 0.f, cB = 0.f;
        if (tid < 64) {
            vA = buf[sl0][2][tid]; cA = cb[sl0];
            vB = buf[sl1][2][tid]; cB = cb[sl1];
        }

        // prefetch steps t+14, t+15 (slots consumed 1-2 iters ago)
        {
            int t0 = t + 14, t1 = t + 15;
            if (t0 < TSEQ) {
                CP4(sbuf + (uint32_t)((t0 & (PF - 1)) * 1024) + mydst, lp + base0 + (size_t)t0 * CDIM + idx);
                if (tid == 0) CP4(scb + (t0 & (PF - 1)) * 4, cv + cvbase + (size_t)t0 * HNUM);
            }
            if (t1 < TSEQ) {
                CP4(sbuf + (uint32_t)((t1 & (PF - 1)) * 1024) + mydst, lp + base0 + (size_t)t1 * CDIM + idx);
                if (tid == 0) CP4(scb + (t1 & (PF - 1)) * 4, cv + cvbase + (size_t)t1 * HNUM);
            }
            CPCOMMIT();
        }
        CPWAIT5();
        __syncthreads();

        if (tid < 64) {
            float yA = ypart[it][0][0][tid] + ypart[it][0][1][tid]
                     + ypart[it][0][2][tid] + ypart[it][0][3][tid] + vA * cA;
            float yB = ypart[it][1][0][tid] + ypart[it][1][1][tid]
                     + ypart[it][1][2][tid] + ypart[it][1][3][tid] + vB * cB;
            y[base0 + (size_t)t * CDIM + tid] = yA;
            y[base0 + (size_t)(t + 1) * CDIM + tid] = yB;
        }
    }

#pragma unroll
    for (int q = 0; q < 16; q++) s_out[sbase + (size_t)q * DDIM] = st[q];
}

// ======================================================================================
// GroupNorm * g -> fp16 hi/lo
// ======================================================================================
__global__ void __launch_bounds__(256) gn_kernel(
    const float* __restrict__ y, const float* __restrict__ g,
    const float* __restrict__ gamma, const float* __restrict__ beta,
    __half* __restrict__ yhi, __half* __restrict__ ylo)
{
    int warp = (blockIdx.x * blockDim.x + threadIdx.x) >> 5;
    int lane = threadIdx.x & 31;
    int m = warp >> 4, h = warp & 15;
    size_t base = (size_t)m * CDIM + h * DDIM;

    float2 vv = *(const float2*)&y[base + lane * 2];
    float s  = vv.x + vv.y;
    float sq = vv.x * vv.x + vv.y * vv.y;
#pragma unroll
    for (int o = 16; o > 0; o >>= 1) {
        s  += __shfl_xor_sync(0xffffffffu, s,  o);
        sq += __shfl_xor_sync(0xffffffffu, sq, o);
    }
    float mean = s * (1.f / 64.f);
    float var  = sq * (1.f / 64.f) - mean * mean;
    float inv  = rsqrtf(var + 1e-5f * (float)HNUM);

    int c0 = h * DDIM + lane * 2;
    float2 gv = *(const float2*)&g[base + lane * 2];
    float o0 = ((vv.x - mean) * inv * gamma[c0]     + beta[c0])     * gv.x;
    float o1 = ((vv.y - mean) * inv * gamma[c0 + 1] + beta[c0 + 1]) * gv.y;

    __half h0 = __float2half_rn(o0), h1 = __float2half_rn(o1);
    __half l0 = __float2half_rn(o0 - __half2float(h0));
    __half l1 = __float2half_rn(o1 - __half2float(h1));
    __half2 H = __halves2half2(h0, h1), L = __halves2half2(l0, l1);
    *(uint32_t*)(yhi + base + lane * 2) = *(uint32_t*)&H;
    *(uint32_t*)(ylo + base + lane * 2) = *(uint32_t*)&L;
}

// ======================================================================================
extern "C" void kernel_launch(void* const* d_in, const int* in_sizes, int n_in,
                              void* d_out, int out_size)
{
    const float* x    = (const float*)d_in[0];
    const float* xlst = (const float*)d_in[1];
    const float* s_in = (const float*)d_in[2];
    const float* miux = (const float*)d_in[3];
    const float* lam  = (const float*)d_in[4];
    const float* Aw   = (const float*)d_in[5];
    const float* Blo5 = (const float*)d_in[6];
    const float* tdm  = (const float*)d_in[7];
    const float* tdA  = (const float*)d_in[8];
    const float* tdB  = (const float*)d_in[9];
    const float* u    = (const float*)d_in[10];
    const float* Wk   = (const float*)d_in[11];
    const float* Wv   = (const float*)d_in[12];
    const float* Wr   = (const float*)d_in[13];
    const float* Wo   = (const float*)d_in[14];
    const float* Wg1  = (const float*)d_in[15];
    const float* Wg2  = (const float*)d_in[16];
    const float* gam  = (const float*)d_in[17];
    const float* bet  = (const float*)d_in[18];
    float* out = (float*)d_out;

    float *t1, *w, *dec, *kb, *vb, *rb, *gb, *yb, *cv;
    __half *xlhi, *xllo, *w0hi, *w0lo, *g0hi, *g0lo, *g1hi, *g1lo, *h1hi, *h1lo;
    __half *khi, *klo, *vhi, *vlo, *rhi, *rlo, *yhi, *ylo, *Whi;
    __half *Athi, *tdAthi, *tdBthi, *G1thi, *G2thi;
    cudaGetSymbolAddress((void**)&t1,  g_t1);
    cudaGetSymbolAddress((void**)&xlhi, g_xlhi); cudaGetSymbolAddress((void**)&xllo, g_xllo);
    cudaGetSymbolAddress((void**)&w0hi, g_w0hi); cudaGetSymbolAddress((void**)&w0lo, g_w0lo);
    cudaGetSymbolAddress((void**)&g0hi, g_g0hi); cudaGetSymbolAddress((void**)&g0lo, g_g0lo);
    cudaGetSymbolAddress((void**)&g1hi, g_g1hi); cudaGetSymbolAddress((void**)&g1lo, g_g1lo);
    cudaGetSymbolAddress((void**)&h1hi, g_h1hi); cudaGetSymbolAddress((void**)&h1lo, g_h1lo);
    cudaGetSymbolAddress((void**)&khi, g_khi); cudaGetSymbolAddress((void**)&klo, g_klo);
    cudaGetSymbolAddress((void**)&vhi, g_vhi); cudaGetSymbolAddress((void**)&vlo, g_vlo);
    cudaGetSymbolAddress((void**)&rhi, g_rhi); cudaGetSymbolAddress((void**)&rlo, g_rlo);
    cudaGetSymbolAddress((void**)&yhi, g_yhi); cudaGetSymbolAddress((void**)&ylo, g_ylo);
    cudaGetSymbolAddress((void**)&Whi, g_Whi);
    cudaGetSymbolAddress((void**)&Athi, g_Athi);
    cudaGetSymbolAddress((void**)&tdAthi, g_tdAthi);
    cudaGetSymbolAddress((void**)&tdBthi, g_tdBthi);
    cudaGetSymbolAddress((void**)&G1thi, g_G1thi);
    cudaGetSymbolAddress((void**)&G2thi, g_G2thi);
    cudaGetSymbolAddress((void**)&w,   g_w);
    cudaGetSymbolAddress((void**)&dec, g_dec);
    cudaGetSymbolAddress((void**)&kb,  g_kb);
    cudaGetSymbolAddress((void**)&vb,  g_vb);
    cudaGetSymbolAddress((void**)&rb,  g_rb);
    cudaGetSymbolAddress((void**)&gb,  g_gb);
    cudaGetSymbolAddress((void**)&yb,  g_yb);
    cudaGetSymbolAddress((void**)&cv,  g_cv);

    const size_t WSZ = (size_t)CDIM * CDIM;
    const size_t MC = (size_t)MROWS * CDIM;
    cudaFuncSetAttribute(mma_gemm16<0, 32>, cudaFuncAttributeMaxDynamicSharedMemorySize, 2 * STG_A);
    cudaFuncSetAttribute(mma_gemm16<0, 5>,  cudaFuncAttributeMaxDynamicSharedMemorySize, 2 * STG_A);
    cudaFuncSetAttribute(mma_gemm16<2, 32>, cudaFuncAttributeMaxDynamicSharedMemorySize, 2 * STG_A);
    cudaFuncSetAttribute(mma_gemm16<3, 32>, cudaFuncAttributeMaxDynamicSharedMemorySize, 2 * STG_A);
    cudaFuncSetAttribute(mma_gemm16<5, 32>, cudaFuncAttributeMaxDynamicSharedMemorySize, 2 * STG_A);
    cudaFuncSetAttribute(mma_gemm16<4, 2>,  cudaFuncAttributeMaxDynamicSharedMemorySize, 2 * STG_A);
    cudaFuncSetAttribute(xdd_fused, cudaFuncAttributeMaxDynamicSharedMemorySize, 81920);

    dim3 thr(256);
    const int wn4 = (int)(WSZ / 4);

    // 1) xl mix -> fp16 hi/lo, x_raw passthrough
    xprep_kernel<<<(int)(MC / 4 / 256), thr>>>(
        (const float4*)x, (const float4*)xlst, miux, xlhi, xllo, (float4*)(out + MC));
    // 2) A weight transpose+pad
    tpad_h<<<(256 * CDIM + 255) / 256, thr>>>(Aw, Athi, CDIM, 160, 256);
    // 3) square-weight casts, z-batched
    {
        SplitBatch sb = { { Wk, Wv, Wr, Wo } };
        split4_kernel<<<dim3((wn4 + 255) / 256, 4), thr>>>(sb, Whi, wn4);
    }
    // 4) t1 = tanh(xl @ A)   (ncu capture target)
    {
        GemmBatch gbat = {};
        gbat.s[0] = { xlhi, xllo, Athi, t1, nullptr };
        mma_gemm16<2, 32><<<dim3(2, MROWS / 128, 1), thr, 2 * STG_A>>>(gbat, CDIM, nullptr, nullptr);
    }

    // 5-6) decay-LoRA weight preps
    tpad_h<<<(128 * CDIM + 255) / 256, thr>>>(tdA, tdAthi, CDIM, 64, 128);
    tpad_h<<<(CDIM * 64 + 255) / 256, thr>>>(tdB, tdBthi, 64, CDIM, CDIM);

    // 7) fused xdd
    xdd_fused<<<dim3(CDIM / 64, MROWS / 64), thr, 81920>>>(
        t1, Blo5, x, xlst, lam, w0hi, w0lo, g0hi, g0lo, khi, klo, vhi, vlo, rhi, rlo);

    // 8) h1 = tanh(w0 @ td_A) -> fp16 hi/lo (stride 64)
    {
        GemmBatch gbat = {};
        gbat.s[0] = { w0hi, w0lo, tdAthi, nullptr, nullptr };
        mma_gemm16<5, 32><<<dim3(1, MROWS / 128, 1), thr, 2 * STG_A>>>(gbat, CDIM, h1hi, h1lo);
    }
    // 9) w = tdm + h1 @ td_B ; dec = exp(-exp(w))   (K=64)
    {
        GemmBatch gbat = {};
        gbat.s[0] = { h1hi, h1lo, tdBthi, w, tdm };
        mma_gemm16<4, 2><<<dim3(CDIM / 128, MROWS / 128, 1), thr, 2 * STG_A>>>(gbat, 64, (__half*)dec, nullptr);
    }

    // 10) k/v/r projections, z-batched
    {
        GemmBatch gbat = {};
        gbat.s[0] = { khi, klo, Whi + 0 * WSZ, kb, w };
        gbat.s[1] = { vhi, vlo, Whi + 1 * WSZ, vb, nullptr };
        gbat.s[2] = { rhi, rlo, Whi + 2 * WSZ, rb, nullptr };
        mma_gemm16<0, 32><<<dim3(CDIM / 128, MROWS / 128, 3), thr, 2 * STG_A>>>(gbat, CDIM, nullptr, nullptr);
    }

    // 11-12) gate weight preps
    tpad_h<<<(256 * CDIM + 255) / 256, thr>>>(Wg1, G1thi, CDIM, 160, 256);
    tpad_h<<<(CDIM * 160 + 255) / 256, thr>>>(Wg2, G2thi, 160, CDIM, CDIM);

    // 13) g1 = tanh(g0 @ W_g1) -> fp16 hi/lo
    {
        GemmBatch gbat = {};
        gbat.s[0] = { g0hi, g0lo, G1thi, nullptr, nullptr };
        mma_gemm16<3, 32><<<dim3(2, MROWS / 128, 1), thr, 2 * STG_A>>>(gbat, CDIM, g1hi, g1lo);
    }
    // 14) g = g1 @ W_g2   (K=160)
    {
        GemmBatch gbat = {};
        gbat.s[0] = { g1hi, g1lo, G2thi, gb, nullptr };
        mma_gemm16<0, 5><<<dim3(CDIM / 128, MROWS / 128, 1), thr, 2 * STG_A>>>(gbat, 160, nullptr, nullptr);
    }

    // 15) cvec precompute
    cvec_kernel<<<(MROWS * HNUM) / 8, thr>>>(rb, kb, u, cv);

    // 16) WKV-6 scan (PF=16 ring, 2 steps/barrier)
    wkv_kernel<<<BSZ * HNUM, thr>>>(rb, kb, vb, dec, cv, s_in, yb, out + 2 * MC);

    // 17) GroupNorm * g -> fp16 hi/lo
    gn_kernel<<<(MROWS * HNUM) / 8, thr>>>(yb, gb, gam, bet, yhi, ylo);

    // 18) out = (yn*g) @ Wo^T
    {
        GemmBatch gbat = {};
        gbat.s[0] = { yhi, ylo, Whi + 3 * WSZ, out, nullptr };
        mma_gemm16<0, 32><<<dim3(CDIM / 128, MROWS / 128, 1), thr, 2 * STG_A>>>(gbat, CDIM, nullptr, nullptr);
    }
}

// round 13
// speedup vs baseline: 1.1506x; 1.1506x over previous
#include <cuda_runtime.h>
#include <cuda_fp16.h>
#include <stdint.h>
#include <math.h>

#define MROWS 16384   // B*T = 8*2048
#define CDIM  1024
#define HNUM  16
#define DDIM  64
#define TSEQ  2048
#define BSZ   8

// ---------------- scratch (static device memory; no runtime allocation) ----------------
__device__ float g_t1 [(size_t)MROWS * 160];
__device__ __half g_xlhi[(size_t)MROWS * CDIM], g_xllo[(size_t)MROWS * CDIM];
__device__ __half g_w0hi[(size_t)MROWS * CDIM], g_w0lo[(size_t)MROWS * CDIM];
__device__ __half g_g0hi[(size_t)MROWS * CDIM], g_g0lo[(size_t)MROWS * CDIM];
__device__ __half g_g1hi[(size_t)MROWS * 160],  g_g1lo[(size_t)MROWS * 160];
__device__ __half g_h1hi[(size_t)MROWS * 64],   g_h1lo[(size_t)MROWS * 64];
__device__ __half g_khi[(size_t)MROWS * CDIM], g_klo[(size_t)MROWS * CDIM];
__device__ __half g_vhi[(size_t)MROWS * CDIM], g_vlo[(size_t)MROWS * CDIM];
__device__ __half g_rhi[(size_t)MROWS * CDIM], g_rlo[(size_t)MROWS * CDIM];
__device__ __half g_yhi[(size_t)MROWS * CDIM], g_ylo[(size_t)MROWS * CDIM];
__device__ __half g_Whi[4][(size_t)CDIM * CDIM];
__device__ __half g_Athi[(size_t)256 * CDIM];
__device__ __half g_tdAthi[(size_t)128 * CDIM];
__device__ __half g_tdBthi[(size_t)CDIM * 64];
__device__ __half g_G1thi[(size_t)256 * CDIM];
__device__ __half g_G2thi[(size_t)CDIM * 160];
__device__ float g_w  [(size_t)MROWS * CDIM];
__device__ float g_dec[(size_t)MROWS * CDIM];
__device__ float g_kb [(size_t)MROWS * CDIM];
__device__ float g_vb [(size_t)MROWS * CDIM];
__device__ float g_rb [(size_t)MROWS * CDIM];
__device__ float g_gb [(size_t)MROWS * CDIM];
__device__ float g_yb [(size_t)MROWS * CDIM];
__device__ float g_cv [(size_t)MROWS * HNUM];

// ======================================================================================
// helpers
// ======================================================================================
__device__ __forceinline__ uint32_t smem_u32(const void* p) {
    uint32_t a;
    asm("{ .reg .u64 t; cvta.to.shared.u64 t, %1; cvt.u32.u64 %0, t; }" : "=r"(a) : "l"(p));
    return a;
}
__device__ __forceinline__ void ldsm4(uint32_t* r, uint32_t addr) {
    asm volatile("ldmatrix.sync.aligned.m8n8.x4.shared.b16 {%0,%1,%2,%3}, [%4];"
        : "=r"(r[0]), "=r"(r[1]), "=r"(r[2]), "=r"(r[3]) : "r"(addr));
}
__device__ __forceinline__ void mma16816(float* c, const uint32_t* a, const uint32_t* b) {
    asm volatile("mma.sync.aligned.m16n8k16.row.col.f32.f16.f16.f32 "
        "{%0,%1,%2,%3}, {%4,%5,%6,%7}, {%8,%9}, {%0,%1,%2,%3};"
        : "+f"(c[0]), "+f"(c[1]), "+f"(c[2]), "+f"(c[3])
        : "r"(a[0]), "r"(a[1]), "r"(a[2]), "r"(a[3]), "r"(b[0]), "r"(b[1]));
}
#define CP16(d, s) asm volatile("cp.async.cg.shared.global [%0], [%1], 16;" :: "r"(d), "l"(s))
#define CP4(d, s)  asm volatile("cp.async.ca.shared.global [%0], [%1], 4;"  :: "r"(d), "l"(s))
#define CPCOMMIT() asm volatile("cp.async.commit_group;" ::: "memory")
#define CPWAIT1()  asm volatile("cp.async.wait_group 1;" ::: "memory")
#define CPWAIT5()  asm volatile("cp.async.wait_group 5;" ::: "memory")

__device__ __forceinline__ void cvt_hilo4h(float4 v, uint2& hi, uint2& lo) {
    __half h0 = __float2half_rn(v.x), h1 = __float2half_rn(v.y);
    __half h2 = __float2half_rn(v.z), h3 = __float2half_rn(v.w);
    __half l0 = __float2half_rn(v.x - __half2float(h0));
    __half l1 = __float2half_rn(v.y - __half2float(h1));
    __half l2 = __float2half_rn(v.z - __half2float(h2));
    __half l3 = __float2half_rn(v.w - __half2float(h3));
    __half2 H01 = __halves2half2(h0, h1), H23 = __halves2half2(h2, h3);
    __half2 L01 = __halves2half2(l0, l1), L23 = __halves2half2(l2, l3);
    hi = make_uint2(*(uint32_t*)&H01, *(uint32_t*)&H23);
    lo = make_uint2(*(uint32_t*)&L01, *(uint32_t*)&L23);
}
__device__ __forceinline__ uint2 cvt_hi4(float4 v) {
    __half2 H01 = __halves2half2(__float2half_rn(v.x), __float2half_rn(v.y));
    __half2 H23 = __halves2half2(__float2half_rn(v.z), __float2half_rn(v.w));
    return make_uint2(*(uint32_t*)&H01, *(uint32_t*)&H23);
}

// ======================================================================================
// prep kernels
// ======================================================================================
struct SplitBatch { const float* src[4]; };

__global__ void __launch_bounds__(256) split4_kernel(
    SplitBatch sb, __half* __restrict__ hi, int n4)
{
    int idx = blockIdx.x * 256 + threadIdx.x;
    if (idx >= n4) return;
    const size_t zoff = (size_t)blockIdx.y * CDIM * CDIM;
    *(uint2*)(hi + zoff + (size_t)idx * 4) = cvt_hi4(((const float4*)sb.src[blockIdx.y])[idx]);
}

__global__ void __launch_bounds__(256) tpad_h(
    const float* __restrict__ in, __half* __restrict__ ohi, int K, int N, int Npad)
{
    int t = blockIdx.x * 256 + threadIdx.x;
    if (t >= Npad * K) return;
    int n = t / K, k = t - n * K;
    float v = (n < N) ? in[(size_t)k * N + n] : 0.f;
    ohi[t] = __float2half_rn(v);
}

__global__ void __launch_bounds__(256) xprep_kernel(
    const float4* __restrict__ x, const float4* __restrict__ xl,
    const float* __restrict__ miux,
    __half* __restrict__ xhi, __half* __restrict__ xlo,
    float4* __restrict__ xraw)
{
    int idx = blockIdx.x * 256 + threadIdx.x;   // MC/4 total
    float4 xv = x[idx], xlv = xl[idx];
    float4 mv = *(const float4*)(miux + (idx & 255) * 4);
    float4 o;
    o.x = fmaf(xlv.x - xv.x, mv.x, xv.x);
    o.y = fmaf(xlv.y - xv.y, mv.y, xv.y);
    o.z = fmaf(xlv.z - xv.z, mv.z, xv.z);
    o.w = fmaf(xlv.w - xv.w, mv.w, xv.w);
    uint2 h, l;
    cvt_hilo4h(o, h, l);
    *(uint2*)(xhi + (size_t)idx * 4) = h;
    *(uint2*)(xlo + (size_t)idx * 4) = l;
    xraw[idx] = xv;
}

// ======================================================================================
// fp16 HMMA GEMM (exact R11 core): C[m,n] = sum_k (Ahi+Alo)[m,k] * Bhi[n,k]
// Tile 128x128, BK=32, KCH chunks, stride kst, 2-stage cp.async, f32 acc both passes.
// EPI 0: fp32 stride CDIM (+exp(min(w,0)) if wptr); 2: tanh fp32 s160;
// 3: tanh fp16 hi/lo s160; 5: tanh fp16 hi/lo s64; 4: +wptr[n], fp32 + exp(-exp())
// ======================================================================================
#define STG_A 30720
#define OAL3  10240
#define OBH3  20480

struct GemmSet {
    const __half *ahi, *alo, *bhi;
    float* c;
    const float* wptr;
};
struct GemmBatch { GemmSet s[3]; };

template <int EPI, int KCH>
__global__ void __launch_bounds__(256, 2) mma_gemm16(
    GemmBatch gbat, int kst, __half* __restrict__ chi, __half* __restrict__ clo)
{
    const GemmSet gs = gbat.s[blockIdx.z];
    extern __shared__ char smem[];
    const int tid = threadIdx.x, wid = tid >> 5, lane = tid & 31;
    const int bm = blockIdx.y, bn = blockIdx.x;
    const uint32_t sbase = smem_u32(smem);

    const int row = tid >> 1, half = tid & 1;
    const __half* pAhi = gs.ahi + (size_t)(bm * 128 + row) * kst + half * 16;
    const __half* pAlo = gs.alo + (size_t)(bm * 128 + row) * kst + half * 16;
    const __half* pBhi = gs.bhi + (size_t)(bn * 128 + row) * kst + half * 16;
    const uint32_t dA = (uint32_t)(row * 80 + half * 32);

    auto issue = [&](int s, int k0) {
        uint32_t sb2 = sbase + s * STG_A;
        CP16(sb2 + dA,             pAhi + k0); CP16(sb2 + dA + 16,        pAhi + k0 + 8);
        CP16(sb2 + OAL3 + dA,      pAlo + k0); CP16(sb2 + OAL3 + dA + 16, pAlo + k0 + 8);
        CP16(sb2 + OBH3 + dA,      pBhi + k0); CP16(sb2 + OBH3 + dA + 16, pBhi + k0 + 8);
    };

    float acc[2][8][4];
#pragma unroll
    for (int a = 0; a < 2; a++)
#pragma unroll
        for (int b = 0; b < 8; b++)
#pragma unroll
            for (int c = 0; c < 4; c++) acc[a][b][c] = 0.f;

    const int arow = (wid & 3) * 32 + (lane & 7) + ((lane >> 3) & 1) * 8;
    const int acol8 = (lane >> 4) * 8;
    const int brow = (wid >> 2) * 64 + ((lane >> 4) << 3) + (lane & 7);
    const int bcol8 = ((lane >> 3) & 1) * 8;

    issue(0, 0);  CPCOMMIT();
    if (KCH > 1) issue(1, 32);
    CPCOMMIT();

    for (int c = 0; c < KCH; c++) {
        CPWAIT1();
        __syncthreads();
        const uint32_t sA = sbase + (c & 1) * STG_A;
#pragma unroll
        for (int ks = 0; ks < 2; ks++) {
            const int kc = ks * 16;
            uint32_t ah[2][4], al[2][4], bh[4][4];
#pragma unroll
            for (int mt = 0; mt < 2; mt++) {
                uint32_t off = (uint32_t)((arow + mt * 16) * 40 + kc + acol8) * 2;
                ldsm4(ah[mt], sA + off);
                ldsm4(al[mt], sA + OAL3 + off);
            }
#pragma unroll
            for (int nt2 = 0; nt2 < 4; nt2++) {
                uint32_t boff = (uint32_t)((brow + nt2 * 16) * 40 + kc + bcol8) * 2;
                ldsm4(bh[nt2], sA + OBH3 + boff);
            }
#pragma unroll
            for (int nt2 = 0; nt2 < 4; nt2++)
#pragma unroll
                for (int mt = 0; mt < 2; mt++) {
                    mma16816(acc[mt][nt2 * 2],     ah[mt], bh[nt2]);
                    mma16816(acc[mt][nt2 * 2 + 1], ah[mt], bh[nt2] + 2);
                }
#pragma unroll
            for (int nt2 = 0; nt2 < 4; nt2++)
#pragma unroll
                for (int mt = 0; mt < 2; mt++) {
                    mma16816(acc[mt][nt2 * 2],     al[mt], bh[nt2]);
                    mma16816(acc[mt][nt2 * 2 + 1], al[mt], bh[nt2] + 2);
                }
        }
        __syncthreads();
        {
            int cn = c + 2;
            if (cn < KCH) issue(cn & 1, cn * 32);
            CPCOMMIT();
        }
    }

    // epilogue
#pragma unroll
    for (int mt = 0; mt < 2; mt++) {
        const int m = bm * 128 + (wid & 3) * 32 + mt * 16 + (lane >> 2);
#pragma unroll
        for (int nt = 0; nt < 8; nt++) {
            const int n = bn * 128 + (wid >> 2) * 64 + nt * 8 + (lane & 3) * 2;
            float c0 = acc[mt][nt][0], c1 = acc[mt][nt][1];
            float c2 = acc[mt][nt][2], c3 = acc[mt][nt][3];
            if (EPI == 0) {
                size_t i0 = (size_t)m * CDIM + n;
                size_t i1 = i0 + (size_t)8 * CDIM;
                if (gs.wptr) {
                    float2 wa = *(const float2*)(gs.wptr + i0);
                    float2 wb = *(const float2*)(gs.wptr + i1);
                    c0 *= __expf(fminf(wa.x, 0.f)); c1 *= __expf(fminf(wa.y, 0.f));
                    c2 *= __expf(fminf(wb.x, 0.f)); c3 *= __expf(fminf(wb.y, 0.f));
                }
                *(float2*)(gs.c + i0) = make_float2(c0, c1);
                *(float2*)(gs.c + i1) = make_float2(c2, c3);
            } else if (EPI == 4) {
                size_t i0 = (size_t)m * CDIM + n;
                size_t i1 = i0 + (size_t)8 * CDIM;
                c0 += gs.wptr[n];     c1 += gs.wptr[n + 1];
                c2 += gs.wptr[n];     c3 += gs.wptr[n + 1];
                float* dec = (float*)chi;
                *(float2*)(gs.c + i0) = make_float2(c0, c1);
                *(float2*)(gs.c + i1) = make_float2(c2, c3);
                *(float2*)(dec + i0) = make_float2(__expf(-__expf(c0)), __expf(-__expf(c1)));
                *(float2*)(dec + i1) = make_float2(__expf(-__expf(c2)), __expf(-__expf(c3)));
            } else {
                const int NS = (EPI == 5) ? 64 : 160;
                if (n >= NS) continue;
                c0 = tanhf(c0); c1 = tanhf(c1); c2 = tanhf(c2); c3 = tanhf(c3);
                size_t i0 = (size_t)m * NS + n;
                size_t i1 = i0 + (size_t)8 * NS;
                if (EPI == 2) {
                    *(float2*)(gs.c + i0) = make_float2(c0, c1);
                    *(float2*)(gs.c + i1) = make_float2(c2, c3);
                } else {
                    __half h0 = __float2half_rn(c0), h1 = __float2half_rn(c1);
                    __half h2 = __float2half_rn(c2), h3 = __float2half_rn(c3);
                    __half l0 = __float2half_rn(c0 - __half2float(h0));
                    __half l1 = __float2half_rn(c1 - __half2float(h1));
                    __half l2 = __float2half_rn(c2 - __half2float(h2));
                    __half l3 = __float2half_rn(c3 - __half2float(h3));
                    __half2 H01 = __halves2half2(h0, h1), H23 = __halves2half2(h2, h3);
                    __half2 L01 = __halves2half2(l0, l1), L23 = __halves2half2(l2, l3);
                    *(uint32_t*)(chi + i0) = *(uint32_t*)&H01;
                    *(uint32_t*)(chi + i1) = *(uint32_t*)&H23;
                    *(uint32_t*)(clo + i0) = *(uint32_t*)&L01;
                    *(uint32_t*)(clo + i1) = *(uint32_t*)&L23;
                }
            }
        }
    }
}

// ======================================================================================
// fused xdd (K=32 LoRA): all 5 outputs -> fp16 hi/lo
// ======================================================================================
__global__ void __launch_bounds__(256) xdd_fused(
    const float* __restrict__ t1, const float* __restrict__ Blo5,
    const float* __restrict__ x, const float* __restrict__ xl,
    const float* __restrict__ lam,
    __half* __restrict__ w0hi, __half* __restrict__ w0lo,
    __half* __restrict__ g0hi, __half* __restrict__ g0lo,
    __half* __restrict__ khi, __half* __restrict__ klo,
    __half* __restrict__ vhi, __half* __restrict__ vlo,
    __half* __restrict__ rhi, __half* __restrict__ rlo)
{
    extern __shared__ float sh[];
    float* T1 = sh;              // [5][64][32]
    float* BL = sh + 10240;      // [5][32][64]
    const int tid = threadIdx.x;
    const int bm = blockIdx.y, bn = blockIdx.x;
    const int tx = tid & 15, ty = tid >> 4;

#pragma unroll
    for (int ii = 0; ii < 10; ii++) {
        int c4 = tid + ii * 256;
        int f = c4 >> 9, rem = c4 & 511;
        int row = rem >> 3, kq = rem & 7;
        float4 v = *(const float4*)(t1 + (size_t)f * MROWS * 32 + (size_t)(bm * 64 + row) * 32 + kq * 4);
        *(float4*)&T1[(f * 64 + row) * 32 + kq * 4] = v;
    }
#pragma unroll
    for (int ii = 0; ii < 10; ii++) {
        int c4 = tid + ii * 256;
        int f = c4 >> 9, rem = c4 & 511;
        int k = rem >> 4, cq = rem & 15;
        float4 v = *(const float4*)(Blo5 + (size_t)f * 32 * CDIM + (size_t)k * CDIM + bn * 64 + cq * 4);
        *(float4*)&BL[(f * 32 + k) * 64 + cq * 4] = v;
    }
    __syncthreads();

    float acc[5][4][4];
#pragma unroll
    for (int f = 0; f < 5; f++)
#pragma unroll
        for (int i = 0; i < 4; i++)
#pragma unroll
            for (int j = 0; j < 4; j++) acc[f][i][j] = 0.f;

    for (int k = 0; k < 32; k++) {
#pragma unroll
        for (int f = 0; f < 5; f++) {
            float4 b = *(const float4*)&BL[(f * 32 + k) * 64 + tx * 4];
            float a0 = T1[(f * 64 + ty * 4 + 0) * 32 + k];
            float a1 = T1[(f * 64 + ty * 4 + 1) * 32 + k];
            float a2 = T1[(f * 64 + ty * 4 + 2) * 32 + k];
            float a3 = T1[(f * 64 + ty * 4 + 3) * 32 + k];
            acc[f][0][0] = fmaf(a0, b.x, acc[f][0][0]); acc[f][0][1] = fmaf(a0, b.y, acc[f][0][1]);
            acc[f][0][2] = fmaf(a0, b.z, acc[f][0][2]); acc[f][0][3] = fmaf(a0, b.w, acc[f][0][3]);
            acc[f][1][0] = fmaf(a1, b.x, acc[f][1][0]); acc[f][1][1] = fmaf(a1, b.y, acc[f][1][1]);
            acc[f][1][2] = fmaf(a1, b.z, acc[f][1][2]); acc[f][1][3] = fmaf(a1, b.w, acc[f][1][3]);
            acc[f][2][0] = fmaf(a2, b.x, acc[f][2][0]); acc[f][2][1] = fmaf(a2, b.y, acc[f][2][1]);
            acc[f][2][2] = fmaf(a2, b.z, acc[f][2][2]); acc[f][2][3] = fmaf(a2, b.w, acc[f][2][3]);
            acc[f][3][0] = fmaf(a3, b.x, acc[f][3][0]); acc[f][3][1] = fmaf(a3, b.y, acc[f][3][1]);
            acc[f][3][2] = fmaf(a3, b.z, acc[f][3][2]); acc[f][3][3] = fmaf(a3, b.w, acc[f][3][3]);
        }
    }

    const int n0 = bn * 64 + tx * 4;
    float4 lamv[5];
#pragma unroll
    for (int f = 0; f < 5; f++) lamv[f] = *(const float4*)(lam + f * CDIM + n0);

#pragma unroll
    for (int i = 0; i < 4; i++) {
        const int m = bm * 64 + ty * 4 + i;
        size_t ix = (size_t)m * CDIM + n0;
        float4 xv = *(const float4*)(x + ix);
        float4 xlv = *(const float4*)(xl + ix);
        float4 ba = make_float4(xlv.x - xv.x, xlv.y - xv.y, xlv.z - xv.z, xlv.w - xv.w);
        float4 o[5];
#pragma unroll
        for (int f = 0; f < 5; f++) {
            o[f].x = fmaf(ba.x, lamv[f].x + acc[f][i][0], xv.x);
            o[f].y = fmaf(ba.y, lamv[f].y + acc[f][i][1], xv.y);
            o[f].z = fmaf(ba.z, lamv[f].z + acc[f][i][2], xv.z);
            o[f].w = fmaf(ba.w, lamv[f].w + acc[f][i][3], xv.w);
        }
        uint2 h, l;
        cvt_hilo4h(o[0], h, l); *(uint2*)(w0hi + ix) = h; *(uint2*)(w0lo + ix) = l;
        cvt_hilo4h(o[1], h, l); *(uint2*)(khi + ix) = h; *(uint2*)(klo + ix) = l;
        cvt_hilo4h(o[2], h, l); *(uint2*)(vhi + ix) = h; *(uint2*)(vlo + ix) = l;
        cvt_hilo4h(o[3], h, l); *(uint2*)(rhi + ix) = h; *(uint2*)(rlo + ix) = l;
        cvt_hilo4h(o[4], h, l); *(uint2*)(g0hi + ix) = h; *(uint2*)(g0lo + ix) = l;
    }
}

// ======================================================================================
// cvec[m,h] = sum_j r*u*k
// ======================================================================================
__global__ void __launch_bounds__(256) cvec_kernel(
    const float* __restrict__ rb, const float* __restrict__ kb,
    const float* __restrict__ u, float* __restrict__ cv)
{
    int gw = (blockIdx.x * 256 + threadIdx.x) >> 5;
    int lane = threadIdx.x & 31;
    int m = gw >> 4, h = gw & 15;
    size_t base = (size_t)m * CDIM + h * DDIM;
    float p = rb[base + lane] * u[h * DDIM + lane] * kb[base + lane]
            + rb[base + 32 + lane] * u[h * DDIM + 32 + lane] * kb[base + 32 + lane];
#pragma unroll
    for (int o = 16; o > 0; o >>= 1) p += __shfl_xor_sync(0xffffffffu, p, o);
    if (lane == 0) cv[(size_t)m * HNUM + h] = p;
}

// ======================================================================================
// WKV-6 scan — 256 threads, PF=16 cp.async ring, TWO steps per barrier (R12 scan)
// ======================================================================================
#define PF 16
__global__ void __launch_bounds__(256) wkv_kernel(
    const float* __restrict__ r, const float* __restrict__ k,
    const float* __restrict__ v, const float* __restrict__ dec,
    const float* __restrict__ cv, const float* __restrict__ s_in,
    float* __restrict__ y, float* __restrict__ s_out)
{
    const int bh = blockIdx.x;
    const int b = bh >> 4, h = bh & 15;
    const int tid = threadIdx.x;
    const int i  = tid & 63;
    const int jg = tid >> 6;
    const int j0 = jg * 16;

    __shared__ float buf[PF][4][64];
    __shared__ float cb[PF];
    __shared__ float ypart[2][2][4][64];

    float st[16];
    size_t sbase = (((size_t)b * HNUM + h) * DDIM + j0) * DDIM + i;
#pragma unroll
    for (int q = 0; q < 16; q++) st[q] = s_in[sbase + (size_t)q * DDIM];

    const int arr = tid >> 6, idx = tid & 63;
    const float* lp = (arr == 0) ? r : (arr == 1) ? k : (arr == 2) ? v : dec;
    const size_t base0 = ((size_t)b * TSEQ) * CDIM + h * DDIM;
    const size_t cvbase = (size_t)(b * TSEQ) * HNUM + h;

    const uint32_t sbuf = smem_u32(&buf[0][0][0]);
    const uint32_t scb  = smem_u32(&cb[0]);
    const uint32_t mydst = (uint32_t)((arr * 64 + idx) * 4);

    for (int p = 0; p < 7; p++) {
        CP4(sbuf + (uint32_t)((2 * p) * 1024) + mydst,     lp + base0 + (size_t)(2 * p) * CDIM + idx);
        CP4(sbuf + (uint32_t)((2 * p + 1) * 1024) + mydst, lp + base0 + (size_t)(2 * p + 1) * CDIM + idx);
        if (tid == 0) {
            CP4(scb + (2 * p) * 4,     cv + cvbase + (size_t)(2 * p) * HNUM);
            CP4(scb + (2 * p + 1) * 4, cv + cvbase + (size_t)(2 * p + 1) * HNUM);
        }
        CPCOMMIT();
    }
    CPWAIT5();
    __syncthreads();

    for (int t = 0; t < TSEQ; t += 2) {
        const int it = (t >> 1) & 1;
        const int sl0 = t & (PF - 1), sl1 = (t + 1) & (PF - 1);

        {
            const float vi = buf[sl0][2][i];
            float acc = 0.f;
#pragma unroll
            for (int q = 0; q < 16; q += 4) {
                float4 r4 = *(const float4*)&buf[sl0][0][j0 + q];
                float4 k4 = *(const float4*)&buf[sl0][1][j0 + q];
                float4 d4 = *(const float4*)&buf[sl0][3][j0 + q];
                acc = fmaf(r4.x, st[q + 0], acc); st[q + 0] = fmaf(d4.x, st[q + 0], k4.x * vi);
                acc = fmaf(r4.y, st[q + 1], acc); st[q + 1] = fmaf(d4.y, st[q + 1], k4.y * vi);
                acc = fmaf(r4.z, st[q + 2], acc); st[q + 2] = fmaf(d4.z, st[q + 2], k4.z * vi);
                acc = fmaf(r4.w, st[q + 3], acc); st[q + 3] = fmaf(d4.w, st[q + 3], k4.w * vi);
            }
            ypart[it][0][jg][i] = acc;
        }
        {
            const float vi = buf[sl1][2][i];
            float acc = 0.f;
#pragma unroll
            for (int q = 0; q < 16; q += 4) {
                float4 r4 = *(const float4*)&buf[sl1][0][j0 + q];
                float4 k4 = *(const float4*)&buf[sl1][1][j0 + q];
                float4 d4 = *(const float4*)&buf[sl1][3][j0 + q];
                acc = fmaf(r4.x, st[q + 0], acc); st[q + 0] = fmaf(d4.x, st[q + 0], k4.x * vi);
                acc = fmaf(r4.y, st[q + 1], acc); st[q + 1] = fmaf(d4.y, st[q + 1], k4.y * vi);
                acc = fmaf(r4.z, st[q + 2], acc); st[q + 2] = fmaf(d4.z, st[q + 2], k4.z * vi);
                acc = fmaf(r4.w, st[q + 3], acc); st[q + 3] = fmaf(d4.w, st[q + 3], k4.w * vi);
            }
            ypart[it][1][jg][i] = acc;
        }

        float vA = 0.f, cA = 0.f, vB = 0.f, cB = 0.f;
        if (tid < 64) {
            vA = buf[sl0][2][tid]; cA = cb[sl0];
            vB = buf[sl1][2][tid]; cB = cb[sl1];
        }

        {
            int t0 = t + 14, t1 = t + 15;
            if (t0 < TSEQ) {
                CP4(sbuf + (uint32_t)((t0 & (PF - 1)) * 1024) + mydst, lp + base0 + (size_t)t0 * CDIM + idx);
                if (tid == 0) CP4(scb + (t0 & (PF - 1)) * 4, cv + cvbase + (size_t)t0 * HNUM);
            }
            if (t1 < TSEQ) {
                CP4(sbuf + (uint32_t)((t1 & (PF - 1)) * 1024) + mydst, lp + base0 + (size_t)t1 * CDIM + idx);
                if (tid == 0) CP4(scb + (t1 & (PF - 1)) * 4, cv + cvbase + (size_t)t1 * HNUM);
            }
            CPCOMMIT();
        }
        CPWAIT5();
        __syncthreads();

        if (tid < 64) {
            float yA = ypart[it][0][0][tid] + ypart[it][0][1][tid]
                     + ypart[it][0][2][tid] + ypart[it][0][3][tid] + vA * cA;
            float yB = ypart[it][1][0][tid] + ypart[it][1][1][tid]
                     + ypart[it][1][2][tid] + ypart[it][1][3][tid] + vB * cB;
            y[base0 + (size_t)t * CDIM + tid] = yA;
            y[base0 + (size_t)(t + 1) * CDIM + tid] = yB;
        }
    }

#pragma unroll
    for (int q = 0; q < 16; q++) s_out[sbase + (size_t)q * DDIM] = st[q];
}

// ======================================================================================
// GroupNorm * g -> fp16 hi/lo
// ======================================================================================
__global__ void __launch_bounds__(256) gn_kernel(
    const float* __restrict__ y, const float* __restrict__ g,
    const float* __restrict__ gamma, const float* __restrict__ beta,
    __half* __restrict__ yhi, __half* __restrict__ ylo)
{
    int warp = (blockIdx.x * blockDim.x + threadIdx.x) >> 5;
    int lane = threadIdx.x & 31;
    int m = warp >> 4, h = warp & 15;
    size_t base = (size_t)m * CDIM + h * DDIM;

    float2 vv = *(const float2*)&y[base + lane * 2];
    float s  = vv.x + vv.y;
    float sq = vv.x * vv.x + vv.y * vv.y;
#pragma unroll
    for (int o = 16; o > 0; o >>= 1) {
        s  += __shfl_xor_sync(0xffffffffu, s,  o);
        sq += __shfl_xor_sync(0xffffffffu, sq, o);
    }
    float mean = s * (1.f / 64.f);
    float var  = sq * (1.f / 64.f) - mean * mean;
    float inv  = rsqrtf(var + 1e-5f * (float)HNUM);

    int c0 = h * DDIM + lane * 2;
    float2 gv = *(const float2*)&g[base + lane * 2];
    float o0 = ((vv.x - mean) * inv * gamma[c0]     + beta[c0])     * gv.x;
    float o1 = ((vv.y - mean) * inv * gamma[c0 + 1] + beta[c0 + 1]) * gv.y;

    __half h0 = __float2half_rn(o0), h1 = __float2half_rn(o1);
    __half l0 = __float2half_rn(o0 - __half2float(h0));
    __half l1 = __float2half_rn(o1 - __half2float(h1));
    __half2 H = __halves2half2(h0, h1), L = __halves2half2(l0, l1);
    *(uint32_t*)(yhi + base + lane * 2) = *(uint32_t*)&H;
    *(uint32_t*)(ylo + base + lane * 2) = *(uint32_t*)&L;
}

// ======================================================================================
extern "C" void kernel_launch(void* const* d_in, const int* in_sizes, int n_in,
                              void* d_out, int out_size)
{
    const float* x    = (const float*)d_in[0];
    const float* xlst = (const float*)d_in[1];
    const float* s_in = (const float*)d_in[2];
    const float* miux = (const float*)d_in[3];
    const float* lam  = (const float*)d_in[4];
    const float* Aw   = (const float*)d_in[5];
    const float* Blo5 = (const float*)d_in[6];
    const float* tdm  = (const float*)d_in[7];
    const float* tdA  = (const float*)d_in[8];
    const float* tdB  = (const float*)d_in[9];
    const float* u    = (const float*)d_in[10];
    const float* Wk   = (const float*)d_in[11];
    const float* Wv   = (const float*)d_in[12];
    const float* Wr   = (const float*)d_in[13];
    const float* Wo   = (const float*)d_in[14];
    const float* Wg1  = (const float*)d_in[15];
    const float* Wg2  = (const float*)d_in[16];
    const float* gam  = (const float*)d_in[17];
    const float* bet  = (const float*)d_in[18];
    float* out = (float*)d_out;

    float *t1, *w, *dec, *kb, *vb, *rb, *gb, *yb, *cv;
    __half *xlhi, *xllo, *w0hi, *w0lo, *g0hi, *g0lo, *g1hi, *g1lo, *h1hi, *h1lo;
    __half *khi, *klo, *vhi, *vlo, *rhi, *rlo, *yhi, *ylo, *Whi;
    __half *Athi, *tdAthi, *tdBthi, *G1thi, *G2thi;
    cudaGetSymbolAddress((void**)&t1,  g_t1);
    cudaGetSymbolAddress((void**)&xlhi, g_xlhi); cudaGetSymbolAddress((void**)&xllo, g_xllo);
    cudaGetSymbolAddress((void**)&w0hi, g_w0hi); cudaGetSymbolAddress((void**)&w0lo, g_w0lo);
    cudaGetSymbolAddress((void**)&g0hi, g_g0hi); cudaGetSymbolAddress((void**)&g0lo, g_g0lo);
    cudaGetSymbolAddress((void**)&g1hi, g_g1hi); cudaGetSymbolAddress((void**)&g1lo, g_g1lo);
    cudaGetSymbolAddress((void**)&h1hi, g_h1hi); cudaGetSymbolAddress((void**)&h1lo, g_h1lo);
    cudaGetSymbolAddress((void**)&khi, g_khi); cudaGetSymbolAddress((void**)&klo, g_klo);
    cudaGetSymbolAddress((void**)&vhi, g_vhi); cudaGetSymbolAddress((void**)&vlo, g_vlo);
    cudaGetSymbolAddress((void**)&rhi, g_rhi); cudaGetSymbolAddress((void**)&rlo, g_rlo);
    cudaGetSymbolAddress((void**)&yhi, g_yhi); cudaGetSymbolAddress((void**)&ylo, g_ylo);
    cudaGetSymbolAddress((void**)&Whi, g_Whi);
    cudaGetSymbolAddress((void**)&Athi, g_Athi);
    cudaGetSymbolAddress((void**)&tdAthi, g_tdAthi);
    cudaGetSymbolAddress((void**)&tdBthi, g_tdBthi);
    cudaGetSymbolAddress((void**)&G1thi, g_G1thi);
    cudaGetSymbolAddress((void**)&G2thi, g_G2thi);
    cudaGetSymbolAddress((void**)&w,   g_w);
    cudaGetSymbolAddress((void**)&dec, g_dec);
    cudaGetSymbolAddress((void**)&kb,  g_kb);
    cudaGetSymbolAddress((void**)&vb,  g_vb);
    cudaGetSymbolAddress((void**)&rb,  g_rb);
    cudaGetSymbolAddress((void**)&gb,  g_gb);
    cudaGetSymbolAddress((void**)&yb,  g_yb);
    cudaGetSymbolAddress((void**)&cv,  g_cv);

    const size_t WSZ = (size_t)CDIM * CDIM;
    const size_t MC = (size_t)MROWS * CDIM;
    cudaFuncSetAttribute(mma_gemm16<0, 32>, cudaFuncAttributeMaxDynamicSharedMemorySize, 2 * STG_A);
    cudaFuncSetAttribute(mma_gemm16<0, 5>,  cudaFuncAttributeMaxDynamicSharedMemorySize, 2 * STG_A);
    cudaFuncSetAttribute(mma_gemm16<2, 32>, cudaFuncAttributeMaxDynamicSharedMemorySize, 2 * STG_A);
    cudaFuncSetAttribute(mma_gemm16<3, 32>, cudaFuncAttributeMaxDynamicSharedMemorySize, 2 * STG_A);
    cudaFuncSetAttribute(mma_gemm16<5, 32>, cudaFuncAttributeMaxDynamicSharedMemorySize, 2 * STG_A);
    cudaFuncSetAttribute(mma_gemm16<4, 2>,  cudaFuncAttributeMaxDynamicSharedMemorySize, 2 * STG_A);
    cudaFuncSetAttribute(xdd_fused, cudaFuncAttributeMaxDynamicSharedMemorySize, 81920);

    dim3 thr(256);
    const int wn4 = (int)(WSZ / 4);

    // 1) xl mix -> fp16 hi/lo, x_raw passthrough
    xprep_kernel<<<(int)(MC / 4 / 256), thr>>>(
        (const float4*)x, (const float4*)xlst, miux, xlhi, xllo, (float4*)(out + MC));
    // 2) A weight transpose+pad
    tpad_h<<<(256 * CDIM + 255) / 256, thr>>>(Aw, Athi, CDIM, 160, 256);
    // 3) square-weight casts, z-batched
    {
        SplitBatch sb = { { Wk, Wv, Wr, Wo } };
        split4_kernel<<<dim3((wn4 + 255) / 256, 4), thr>>>(sb, Whi, wn4);
    }
    // 4) t1 = tanh(xl @ A)   (ncu capture target)
    {
        GemmBatch gbat = {};
        gbat.s[0] = { xlhi, xllo, Athi, t1, nullptr };
        mma_gemm16<2, 32><<<dim3(2, MROWS / 128, 1), thr, 2 * STG_A>>>(gbat, CDIM, nullptr, nullptr);
    }

    // 5-6) decay-LoRA weight preps
    tpad_h<<<(128 * CDIM + 255) / 256, thr>>>(tdA, tdAthi, CDIM, 64, 128);
    tpad_h<<<(CDIM * 64 + 255) / 256, thr>>>(tdB, tdBthi, 64, CDIM, CDIM);

    // 7) fused xdd
    xdd_fused<<<dim3(CDIM / 64, MROWS / 64), thr, 81920>>>(
        t1, Blo5, x, xlst, lam, w0hi, w0lo, g0hi, g0lo, khi, klo, vhi, vlo, rhi, rlo);

    // 8) h1 = tanh(w0 @ td_A) -> fp16 hi/lo (stride 64)
    {
        GemmBatch gbat = {};
        gbat.s[0] = { w0hi, w0lo, tdAthi, nullptr, nullptr };
        mma_gemm16<5, 32><<<dim3(1, MROWS / 128, 1), thr, 2 * STG_A>>>(gbat, CDIM, h1hi, h1lo);
    }
    // 9) w = tdm + h1 @ td_B ; dec = exp(-exp(w))   (K=64)
    {
        GemmBatch gbat = {};
        gbat.s[0] = { h1hi, h1lo, tdBthi, w, tdm };
        mma_gemm16<4, 2><<<dim3(CDIM / 128, MROWS / 128, 1), thr, 2 * STG_A>>>(gbat, 64, (__half*)dec, nullptr);
    }

    // 10) k/v/r projections, z-batched
    {
        GemmBatch gbat = {};
        gbat.s[0] = { khi, klo, Whi + 0 * WSZ, kb, w };
        gbat.s[1] = { vhi, vlo, Whi + 1 * WSZ, vb, nullptr };
        gbat.s[2] = { rhi, rlo, Whi + 2 * WSZ, rb, nullptr };
        mma_gemm16<0, 32><<<dim3(CDIM / 128, MROWS / 128, 3), thr, 2 * STG_A>>>(gbat, CDIM, nullptr, nullptr);
    }

    // 11-12) gate weight preps
    tpad_h<<<(256 * CDIM + 255) / 256, thr>>>(Wg1, G1thi, CDIM, 160, 256);
    tpad_h<<<(CDIM * 160 + 255) / 256, thr>>>(Wg2, G2thi, 160, CDIM, CDIM);

    // 13) g1 = tanh(g0 @ W_g1) -> fp16 hi/lo
    {
        GemmBatch gbat = {};
        gbat.s[0] = { g0hi, g0lo, G1thi, nullptr, nullptr };
        mma_gemm16<3, 32><<<dim3(2, MROWS / 128, 1), thr, 2 * STG_A>>>(gbat, CDIM, g1hi, g1lo);
    }
    // 14) g = g1 @ W_g2   (K=160)
    {
        GemmBatch gbat = {};
        gbat.s[0] = { g1hi, g1lo, G2thi, gb, nullptr };
        mma_gemm16<0, 5><<<dim3(CDIM / 128, MROWS / 128, 1), thr, 2 * STG_A>>>(gbat, 160, nullptr, nullptr);
    }

    // 15) cvec precompute
    cvec_kernel<<<(MROWS * HNUM) / 8, thr>>>(rb, kb, u, cv);

    // 16) WKV-6 scan (PF=16 ring, 2 steps/barrier)
    wkv_kernel<<<BSZ * HNUM, thr>>>(rb, kb, vb, dec, cv, s_in, yb, out + 2 * MC);

    // 17) GroupNorm * g -> fp16 hi/lo
    gn_kernel<<<(MROWS * HNUM) / 8, thr>>>(yb, gb, gam, bet, yhi, ylo);

    // 18) out = (yn*g) @ Wo^T
    {
        GemmBatch gbat = {};
        gbat.s[0] = { yhi, ylo, Whi + 3 * WSZ, out, nullptr };
        mma_gemm16<0, 32><<<dim3(CDIM / 128, MROWS / 128, 1), thr, 2 * STG_A>>>(gbat, CDIM, nullptr, nullptr);
    }
}

// round 14
// speedup vs baseline: 1.2278x; 1.0671x over previous
#include <cuda_runtime.h>
#include <cuda_fp16.h>
#include <stdint.h>
#include <math.h>

#define MROWS 16384   // B*T = 8*2048
#define CDIM  1024
#define HNUM  16
#define DDIM  64
#define TSEQ  2048
#define BSZ   8

// ---------------- scratch (static device memory; no runtime allocation) ----------------
__device__ float g_t1 [(size_t)MROWS * 160];
__device__ __half g_xlhi[(size_t)MROWS * CDIM], g_xllo[(size_t)MROWS * CDIM];
__device__ __half g_w0hi[(size_t)MROWS * CDIM], g_w0lo[(size_t)MROWS * CDIM];
__device__ __half g_g0hi[(size_t)MROWS * CDIM], g_g0lo[(size_t)MROWS * CDIM];
__device__ __half g_g1hi[(size_t)MROWS * 160],  g_g1lo[(size_t)MROWS * 160];
__device__ __half g_h1hi[(size_t)MROWS * 64],   g_h1lo[(size_t)MROWS * 64];
__device__ __half g_khi[(size_t)MROWS * CDIM], g_klo[(size_t)MROWS * CDIM];
__device__ __half g_vhi[(size_t)MROWS * CDIM], g_vlo[(size_t)MROWS * CDIM];
__device__ __half g_rhi[(size_t)MROWS * CDIM], g_rlo[(size_t)MROWS * CDIM];
__device__ __half g_yhi[(size_t)MROWS * CDIM];
__device__ __half g_Whi[4][(size_t)CDIM * CDIM];
__device__ __half g_Athi[(size_t)256 * CDIM];
__device__ __half g_tdAthi[(size_t)128 * CDIM];
__device__ __half g_tdBthi[(size_t)CDIM * 64];
__device__ __half g_G1thi[(size_t)256 * CDIM];
__device__ __half g_G2thi[(size_t)CDIM * 160];
__device__ float g_w  [(size_t)MROWS * CDIM];
__device__ float g_dec[(size_t)MROWS * CDIM];
__device__ float g_kb [(size_t)MROWS * CDIM];
__device__ float g_vb [(size_t)MROWS * CDIM];
__device__ float g_rb [(size_t)MROWS * CDIM];
__device__ float g_gb [(size_t)MROWS * CDIM];
__device__ float g_yb [(size_t)MROWS * CDIM];
__device__ float g_cv [(size_t)MROWS * HNUM];

// ======================================================================================
// helpers
// ======================================================================================
__device__ __forceinline__ uint32_t smem_u32(const void* p) {
    uint32_t a;
    asm("{ .reg .u64 t; cvta.to.shared.u64 t, %1; cvt.u32.u64 %0, t; }" : "=r"(a) : "l"(p));
    return a;
}
__device__ __forceinline__ void ldsm4(uint32_t* r, uint32_t addr) {
    asm volatile("ldmatrix.sync.aligned.m8n8.x4.shared.b16 {%0,%1,%2,%3}, [%4];"
        : "=r"(r[0]), "=r"(r[1]), "=r"(r[2]), "=r"(r[3]) : "r"(addr));
}
__device__ __forceinline__ void mma16816(float* c, const uint32_t* a, const uint32_t* b) {
    asm volatile("mma.sync.aligned.m16n8k16.row.col.f32.f16.f16.f32 "
        "{%0,%1,%2,%3}, {%4,%5,%6,%7}, {%8,%9}, {%0,%1,%2,%3};"
        : "+f"(c[0]), "+f"(c[1]), "+f"(c[2]), "+f"(c[3])
        : "r"(a[0]), "r"(a[1]), "r"(a[2]), "r"(a[3]), "r"(b[0]), "r"(b[1]));
}
#define CP16(d, s) asm volatile("cp.async.cg.shared.global [%0], [%1], 16;" :: "r"(d), "l"(s))
#define CP4(d, s)  asm volatile("cp.async.ca.shared.global [%0], [%1], 4;"  :: "r"(d), "l"(s))
#define CPCOMMIT() asm volatile("cp.async.commit_group;" ::: "memory")
#define CPWAIT1()  asm volatile("cp.async.wait_group 1;" ::: "memory")
#define CPWAIT5()  asm volatile("cp.async.wait_group 5;" ::: "memory")

__device__ __forceinline__ void cvt_hilo4h(float4 v, uint2& hi, uint2& lo) {
    __half h0 = __float2half_rn(v.x), h1 = __float2half_rn(v.y);
    __half h2 = __float2half_rn(v.z), h3 = __float2half_rn(v.w);
    __half l0 = __float2half_rn(v.x - __half2float(h0));
    __half l1 = __float2half_rn(v.y - __half2float(h1));
    __half l2 = __float2half_rn(v.z - __half2float(h2));
    __half l3 = __float2half_rn(v.w - __half2float(h3));
    __half2 H01 = __halves2half2(h0, h1), H23 = __halves2half2(h2, h3);
    __half2 L01 = __halves2half2(l0, l1), L23 = __halves2half2(l2, l3);
    hi = make_uint2(*(uint32_t*)&H01, *(uint32_t*)&H23);
    lo = make_uint2(*(uint32_t*)&L01, *(uint32_t*)&L23);
}
__device__ __forceinline__ uint2 cvt_hi4(float4 v) {
    __half2 H01 = __halves2half2(__float2half_rn(v.x), __float2half_rn(v.y));
    __half2 H23 = __halves2half2(__float2half_rn(v.z), __float2half_rn(v.w));
    return make_uint2(*(uint32_t*)&H01, *(uint32_t*)&H23);
}

// ======================================================================================
// prep kernels
// ======================================================================================
struct SplitBatch { const float* src[4]; };

__global__ void __launch_bounds__(256) split4_kernel(
    SplitBatch sb, __half* __restrict__ hi, int n4)
{
    int idx = blockIdx.x * 256 + threadIdx.x;
    if (idx >= n4) return;
    const size_t zoff = (size_t)blockIdx.y * CDIM * CDIM;
    *(uint2*)(hi + zoff + (size_t)idx * 4) = cvt_hi4(((const float4*)sb.src[blockIdx.y])[idx]);
}

__global__ void __launch_bounds__(256) tpad_h(
    const float* __restrict__ in, __half* __restrict__ ohi, int K, int N, int Npad)
{
    int t = blockIdx.x * 256 + threadIdx.x;
    if (t >= Npad * K) return;
    int n = t / K, k = t - n * K;
    float v = (n < N) ? in[(size_t)k * N + n] : 0.f;
    ohi[t] = __float2half_rn(v);
}

__global__ void __launch_bounds__(256) xprep_kernel(
    const float4* __restrict__ x, const float4* __restrict__ xl,
    const float* __restrict__ miux,
    __half* __restrict__ xhi, __half* __restrict__ xlo,
    float4* __restrict__ xraw)
{
    int idx = blockIdx.x * 256 + threadIdx.x;   // MC/4 total
    float4 xv = x[idx], xlv = xl[idx];
    float4 mv = *(const float4*)(miux + (idx & 255) * 4);
    float4 o;
    o.x = fmaf(xlv.x - xv.x, mv.x, xv.x);
    o.y = fmaf(xlv.y - xv.y, mv.y, xv.y);
    o.z = fmaf(xlv.z - xv.z, mv.z, xv.z);
    o.w = fmaf(xlv.w - xv.w, mv.w, xv.w);
    uint2 h, l;
    cvt_hilo4h(o, h, l);
    *(uint2*)(xhi + (size_t)idx * 4) = h;
    *(uint2*)(xlo + (size_t)idx * 4) = l;
    xraw[idx] = xv;
}

// ======================================================================================
// fp16 HMMA GEMM: C[m,n] = sum_k (Ahi [+ Alo if TWO])[m,k] * Bhi[n,k]
// Tile 128x128, BK=32, KCH chunks, stride kst, 2-stage cp.async, f32 acc.
// EPI 0: fp32 stride CDIM (+exp(min(w,0)) if wptr); 2: tanh fp32 s160;
// 3: tanh fp16 hi/lo s160; 5: tanh fp16 hi/lo s64; 4: +wptr[n], fp32 + exp(-exp());
// 6: fp16 hi only, stride CDIM (out of gn? unused) -- not used
// ======================================================================================
#define STG_A 30720
#define OAL3  10240
#define OBH3  20480

struct GemmSet {
    const __half *ahi, *alo, *bhi;
    float* c;
    const float* wptr;
};
struct GemmBatch { GemmSet s[3]; };

template <int EPI, int KCH, int TWO>
__global__ void __launch_bounds__(256, 2) mma_gemm16(
    GemmBatch gbat, int kst, __half* __restrict__ chi, __half* __restrict__ clo)
{
    const GemmSet gs = gbat.s[blockIdx.z];
    extern __shared__ char smem[];
    const int tid = threadIdx.x, wid = tid >> 5, lane = tid & 31;
    const int bm = blockIdx.y, bn = blockIdx.x;
    const uint32_t sbase = smem_u32(smem);

    const int row = tid >> 1, half = tid & 1;
    const __half* pAhi = gs.ahi + (size_t)(bm * 128 + row) * kst + half * 16;
    const __half* pAlo = TWO ? gs.alo + (size_t)(bm * 128 + row) * kst + half * 16 : nullptr;
    const __half* pBhi = gs.bhi + (size_t)(bn * 128 + row) * kst + half * 16;
    const uint32_t dA = (uint32_t)(row * 80 + half * 32);

    auto issue = [&](int s, int k0) {
        uint32_t sb2 = sbase + s * STG_A;
        CP16(sb2 + dA,             pAhi + k0); CP16(sb2 + dA + 16,        pAhi + k0 + 8);
        if (TWO) {
            CP16(sb2 + OAL3 + dA,      pAlo + k0);
            CP16(sb2 + OAL3 + dA + 16, pAlo + k0 + 8);
        }
        CP16(sb2 + OBH3 + dA,      pBhi + k0); CP16(sb2 + OBH3 + dA + 16, pBhi + k0 + 8);
    };

    float acc[2][8][4];
#pragma unroll
    for (int a = 0; a < 2; a++)
#pragma unroll
        for (int b = 0; b < 8; b++)
#pragma unroll
            for (int c = 0; c < 4; c++) acc[a][b][c] = 0.f;

    const int arow = (wid & 3) * 32 + (lane & 7) + ((lane >> 3) & 1) * 8;
    const int acol8 = (lane >> 4) * 8;
    const int brow = (wid >> 2) * 64 + ((lane >> 4) << 3) + (lane & 7);
    const int bcol8 = ((lane >> 3) & 1) * 8;

    issue(0, 0);  CPCOMMIT();
    if (KCH > 1) issue(1, 32);
    CPCOMMIT();

    for (int c = 0; c < KCH; c++) {
        CPWAIT1();
        __syncthreads();
        const uint32_t sA = sbase + (c & 1) * STG_A;
#pragma unroll
        for (int ks = 0; ks < 2; ks++) {
            const int kc = ks * 16;
            uint32_t ah[2][4], al[2][4], bh[4][4];
#pragma unroll
            for (int mt = 0; mt < 2; mt++) {
                uint32_t off = (uint32_t)((arow + mt * 16) * 40 + kc + acol8) * 2;
                ldsm4(ah[mt], sA + off);
                if (TWO) ldsm4(al[mt], sA + OAL3 + off);
            }
#pragma unroll
            for (int nt2 = 0; nt2 < 4; nt2++) {
                uint32_t boff = (uint32_t)((brow + nt2 * 16) * 40 + kc + bcol8) * 2;
                ldsm4(bh[nt2], sA + OBH3 + boff);
            }
#pragma unroll
            for (int nt2 = 0; nt2 < 4; nt2++)
#pragma unroll
                for (int mt = 0; mt < 2; mt++) {
                    mma16816(acc[mt][nt2 * 2],     ah[mt], bh[nt2]);
                    mma16816(acc[mt][nt2 * 2 + 1], ah[mt], bh[nt2] + 2);
                }
            if (TWO) {
#pragma unroll
                for (int nt2 = 0; nt2 < 4; nt2++)
#pragma unroll
                    for (int mt = 0; mt < 2; mt++) {
                        mma16816(acc[mt][nt2 * 2],     al[mt], bh[nt2]);
                        mma16816(acc[mt][nt2 * 2 + 1], al[mt], bh[nt2] + 2);
                    }
            }
        }
        __syncthreads();
        {
            int cn = c + 2;
            if (cn < KCH) issue(cn & 1, cn * 32);
            CPCOMMIT();
        }
    }

    // epilogue
#pragma unroll
    for (int mt = 0; mt < 2; mt++) {
        const int m = bm * 128 + (wid & 3) * 32 + mt * 16 + (lane >> 2);
#pragma unroll
        for (int nt = 0; nt < 8; nt++) {
            const int n = bn * 128 + (wid >> 2) * 64 + nt * 8 + (lane & 3) * 2;
            float c0 = acc[mt][nt][0], c1 = acc[mt][nt][1];
            float c2 = acc[mt][nt][2], c3 = acc[mt][nt][3];
            if (EPI == 0) {
                size_t i0 = (size_t)m * CDIM + n;
                size_t i1 = i0 + (size_t)8 * CDIM;
                if (gs.wptr) {
                    float2 wa = *(const float2*)(gs.wptr + i0);
                    float2 wb = *(const float2*)(gs.wptr + i1);
                    c0 *= __expf(fminf(wa.x, 0.f)); c1 *= __expf(fminf(wa.y, 0.f));
                    c2 *= __expf(fminf(wb.x, 0.f)); c3 *= __expf(fminf(wb.y, 0.f));
                }
                *(float2*)(gs.c + i0) = make_float2(c0, c1);
                *(float2*)(gs.c + i1) = make_float2(c2, c3);
            } else if (EPI == 4) {
                size_t i0 = (size_t)m * CDIM + n;
                size_t i1 = i0 + (size_t)8 * CDIM;
                c0 += gs.wptr[n];     c1 += gs.wptr[n + 1];
                c2 += gs.wptr[n];     c3 += gs.wptr[n + 1];
                float* dec = (float*)chi;
                *(float2*)(gs.c + i0) = make_float2(c0, c1);
                *(float2*)(gs.c + i1) = make_float2(c2, c3);
                *(float2*)(dec + i0) = make_float2(__expf(-__expf(c0)), __expf(-__expf(c1)));
                *(float2*)(dec + i1) = make_float2(__expf(-__expf(c2)), __expf(-__expf(c3)));
            } else {
                const int NS = (EPI == 5) ? 64 : 160;
                if (n >= NS) continue;
                c0 = tanhf(c0); c1 = tanhf(c1); c2 = tanhf(c2); c3 = tanhf(c3);
                size_t i0 = (size_t)m * NS + n;
                size_t i1 = i0 + (size_t)8 * NS;
                if (EPI == 2) {
                    *(float2*)(gs.c + i0) = make_float2(c0, c1);
                    *(float2*)(gs.c + i1) = make_float2(c2, c3);
                } else {
                    __half h0 = __float2half_rn(c0), h1 = __float2half_rn(c1);
                    __half h2 = __float2half_rn(c2), h3 = __float2half_rn(c3);
                    __half l0 = __float2half_rn(c0 - __half2float(h0));
                    __half l1 = __float2half_rn(c1 - __half2float(h1));
                    __half l2 = __float2half_rn(c2 - __half2float(h2));
                    __half l3 = __float2half_rn(c3 - __half2float(h3));
                    __half2 H01 = __halves2half2(h0, h1), H23 = __halves2half2(h2, h3);
                    __half2 L01 = __halves2half2(l0, l1), L23 = __halves2half2(l2, l3);
                    *(uint32_t*)(chi + i0) = *(uint32_t*)&H01;
                    *(uint32_t*)(chi + i1) = *(uint32_t*)&H23;
                    *(uint32_t*)(clo + i0) = *(uint32_t*)&L01;
                    *(uint32_t*)(clo + i1) = *(uint32_t*)&L23;
                }
            }
        }
    }
}

// ======================================================================================
// fused xdd (K=32 LoRA): all 5 outputs -> fp16 hi/lo
// ======================================================================================
__global__ void __launch_bounds__(256) xdd_fused(
    const float* __restrict__ t1, const float* __restrict__ Blo5,
    const float* __restrict__ x, const float* __restrict__ xl,
    const float* __restrict__ lam,
    __half* __restrict__ w0hi, __half* __restrict__ w0lo,
    __half* __restrict__ g0hi, __half* __restrict__ g0lo,
    __half* __restrict__ khi, __half* __restrict__ klo,
    __half* __restrict__ vhi, __half* __restrict__ vlo,
    __half* __restrict__ rhi, __half* __restrict__ rlo)
{
    extern __shared__ float sh[];
    float* T1 = sh;              // [5][64][32]
    float* BL = sh + 10240;      // [5][32][64]
    const int tid = threadIdx.x;
    const int bm = blockIdx.y, bn = blockIdx.x;
    const int tx = tid & 15, ty = tid >> 4;

#pragma unroll
    for (int ii = 0; ii < 10; ii++) {
        int c4 = tid + ii * 256;
        int f = c4 >> 9, rem = c4 & 511;
        int row = rem >> 3, kq = rem & 7;
        float4 v = *(const float4*)(t1 + (size_t)f * MROWS * 32 + (size_t)(bm * 64 + row) * 32 + kq * 4);
        *(float4*)&T1[(f * 64 + row) * 32 + kq * 4] = v;
    }
#pragma unroll
    for (int ii = 0; ii < 10; ii++) {
        int c4 = tid + ii * 256;
        int f = c4 >> 9, rem = c4 & 511;
        int k = rem >> 4, cq = rem & 15;
        float4 v = *(const float4*)(Blo5 + (size_t)f * 32 * CDIM + (size_t)k * CDIM + bn * 64 + cq * 4);
        *(float4*)&BL[(f * 32 + k) * 64 + cq * 4] = v;
    }
    __syncthreads();

    float acc[5][4][4];
#pragma unroll
    for (int f = 0; f < 5; f++)
#pragma unroll
        for (int i = 0; i < 4; i++)
#pragma unroll
            for (int j = 0; j < 4; j++) acc[f][i][j] = 0.f;

    for (int k = 0; k < 32; k++) {
#pragma unroll
        for (int f = 0; f < 5; f++) {
            float4 b = *(const float4*)&BL[(f * 32 + k) * 64 + tx * 4];
            float a0 = T1[(f * 64 + ty * 4 + 0) * 32 + k];
            float a1 = T1[(f * 64 + ty * 4 + 1) * 32 + k];
            float a2 = T1[(f * 64 + ty * 4 + 2) * 32 + k];
            float a3 = T1[(f * 64 + ty * 4 + 3) * 32 + k];
            acc[f][0][0] = fmaf(a0, b.x, acc[f][0][0]); acc[f][0][1] = fmaf(a0, b.y, acc[f][0][1]);
            acc[f][0][2] = fmaf(a0, b.z, acc[f][0][2]); acc[f][0][3] = fmaf(a0, b.w, acc[f][0][3]);
            acc[f][1][0] = fmaf(a1, b.x, acc[f][1][0]); acc[f][1][1] = fmaf(a1, b.y, acc[f][1][1]);
            acc[f][1][2] = fmaf(a1, b.z, acc[f][1][2]); acc[f][1][3] = fmaf(a1, b.w, acc[f][1][3]);
            acc[f][2][0] = fmaf(a2, b.x, acc[f][2][0]); acc[f][2][1] = fmaf(a2, b.y, acc[f][2][1]);
            acc[f][2][2] = fmaf(a2, b.z, acc[f][2][2]); acc[f][2][3] = fmaf(a2, b.w, acc[f][2][3]);
            acc[f][3][0] = fmaf(a3, b.x, acc[f][3][0]); acc[f][3][1] = fmaf(a3, b.y, acc[f][3][1]);
            acc[f][3][2] = fmaf(a3, b.z, acc[f][3][2]); acc[f][3][3] = fmaf(a3, b.w, acc[f][3][3]);
        }
    }

    const int n0 = bn * 64 + tx * 4;
    float4 lamv[5];
#pragma unroll
    for (int f = 0; f < 5; f++) lamv[f] = *(const float4*)(lam + f * CDIM + n0);

#pragma unroll
    for (int i = 0; i < 4; i++) {
        const int m = bm * 64 + ty * 4 + i;
        size_t ix = (size_t)m * CDIM + n0;
        float4 xv = *(const float4*)(x + ix);
        float4 xlv = *(const float4*)(xl + ix);
        float4 ba = make_float4(xlv.x - xv.x, xlv.y - xv.y, xlv.z - xv.z, xlv.w - xv.w);
        float4 o[5];
#pragma unroll
        for (int f = 0; f < 5; f++) {
            o[f].x = fmaf(ba.x, lamv[f].x + acc[f][i][0], xv.x);
            o[f].y = fmaf(ba.y, lamv[f].y + acc[f][i][1], xv.y);
            o[f].z = fmaf(ba.z, lamv[f].z + acc[f][i][2], xv.z);
            o[f].w = fmaf(ba.w, lamv[f].w + acc[f][i][3], xv.w);
        }
        uint2 h, l;
        cvt_hilo4h(o[0], h, l); *(uint2*)(w0hi + ix) = h; *(uint2*)(w0lo + ix) = l;
        cvt_hilo4h(o[1], h, l); *(uint2*)(khi + ix) = h; *(uint2*)(klo + ix) = l;
        cvt_hilo4h(o[2], h, l); *(uint2*)(vhi + ix) = h; *(uint2*)(vlo + ix) = l;
        cvt_hilo4h(o[3], h, l); *(uint2*)(rhi + ix) = h; *(uint2*)(rlo + ix) = l;
        cvt_hilo4h(o[4], h, l); *(uint2*)(g0hi + ix) = h; *(uint2*)(g0lo + ix) = l;
    }
}

// ======================================================================================
// cvec[m,h] = sum_j r*u*k
// ======================================================================================
__global__ void __launch_bounds__(256) cvec_kernel(
    const float* __restrict__ rb, const float* __restrict__ kb,
    const float* __restrict__ u, float* __restrict__ cv)
{
    int gw = (blockIdx.x * 256 + threadIdx.x) >> 5;
    int lane = threadIdx.x & 31;
    int m = gw >> 4, h = gw & 15;
    size_t base = (size_t)m * CDIM + h * DDIM;
    float p = rb[base + lane] * u[h * DDIM + lane] * kb[base + lane]
            + rb[base + 32 + lane] * u[h * DDIM + 32 + lane] * kb[base + 32 + lane];
#pragma unroll
    for (int o = 16; o > 0; o >>= 1) p += __shfl_xor_sync(0xffffffffu, p, o);
    if (lane == 0) cv[(size_t)m * HNUM + h] = p;
}

// ======================================================================================
// WKV-6 scan — 256 threads, PF=16 cp.async ring, TWO steps per barrier
// ======================================================================================
#define PF 16
__global__ void __launch_bounds__(256) wkv_kernel(
    const float* __restrict__ r, const float* __restrict__ k,
    const float* __restrict__ v, const float* __restrict__ dec,
    const float* __restrict__ cv, const float* __restrict__ s_in,
    float* __restrict__ y, float* __restrict__ s_out)
{
    const int bh = blockIdx.x;
    const int b = bh >> 4, h = bh & 15;
    const int tid = threadIdx.x;
    const int i  = tid & 63;
    const int jg = tid >> 6;
    const int j0 = jg * 16;

    __shared__ float buf[PF][4][64];
    __shared__ float cb[PF];
    __shared__ float ypart[2][2][4][64];

    float st[16];
    size_t sbase = (((size_t)b * HNUM + h) * DDIM + j0) * DDIM + i;
#pragma unroll
    for (int q = 0; q < 16; q++) st[q] = s_in[sbase + (size_t)q * DDIM];

    const int arr = tid >> 6, idx = tid & 63;
    const float* lp = (arr == 0) ? r : (arr == 1) ? k : (arr == 2) ? v : dec;
    const size_t base0 = ((size_t)b * TSEQ) * CDIM + h * DDIM;
    const size_t cvbase = (size_t)(b * TSEQ) * HNUM + h;

    const uint32_t sbuf = smem_u32(&buf[0][0][0]);
    const uint32_t scb  = smem_u32(&cb[0]);
    const uint32_t mydst = (uint32_t)((arr * 64 + idx) * 4);

    for (int p = 0; p < 7; p++) {
        CP4(sbuf + (uint32_t)((2 * p) * 1024) + mydst,     lp + base0 + (size_t)(2 * p) * CDIM + idx);
        CP4(sbuf + (uint32_t)((2 * p + 1) * 1024) + mydst, lp + base0 + (size_t)(2 * p + 1) * CDIM + idx);
        if (tid == 0) {
            CP4(scb + (2 * p) * 4,     cv + cvbase + (size_t)(2 * p) * HNUM);
            CP4(scb + (2 * p + 1) * 4, cv + cvbase + (size_t)(2 * p + 1) * HNUM);
        }
        CPCOMMIT();
    }
    CPWAIT5();
    __syncthreads();

    for (int t = 0; t < TSEQ; t += 2) {
        const int it = (t >> 1) & 1;
        const int sl0 = t & (PF - 1), sl1 = (t + 1) & (PF - 1);

        {
            const float vi = buf[sl0][2][i];
            float acc = 0.f;
#pragma unroll
            for (int q = 0; q < 16; q += 4) {
                float4 r4 = *(const float4*)&buf[sl0][0][j0 + q];
                float4 k4 = *(const float4*)&buf[sl0][1][j0 + q];
                float4 d4 = *(const float4*)&buf[sl0][3][j0 + q];
                acc = fmaf(r4.x, st[q + 0], acc); st[q + 0] = fmaf(d4.x, st[q + 0], k4.x * vi);
                acc = fmaf(r4.y, st[q + 1], acc); st[q + 1] = fmaf(d4.y, st[q + 1], k4.y * vi);
                acc = fmaf(r4.z, st[q + 2], acc); st[q + 2] = fmaf(d4.z, st[q + 2], k4.z * vi);
                acc = fmaf(r4.w, st[q + 3], acc); st[q + 3] = fmaf(d4.w, st[q + 3], k4.w * vi);
            }
            ypart[it][0][jg][i] = acc;
        }
        {
            const float vi = buf[sl1][2][i];
            float acc = 0.f;
#pragma unroll
            for (int q = 0; q < 16; q += 4) {
                float4 r4 = *(const float4*)&buf[sl1][0][j0 + q];
                float4 k4 = *(const float4*)&buf[sl1][1][j0 + q];
                float4 d4 = *(const float4*)&buf[sl1][3][j0 + q];
                acc = fmaf(r4.x, st[q + 0], acc); st[q + 0] = fmaf(d4.x, st[q + 0], k4.x * vi);
                acc = fmaf(r4.y, st[q + 1], acc); st[q + 1] = fmaf(d4.y, st[q + 1], k4.y * vi);
                acc = fmaf(r4.z, st[q + 2], acc); st[q + 2] = fmaf(d4.z, st[q + 2], k4.z * vi);
                acc = fmaf(r4.w, st[q + 3], acc); st[q + 3] = fmaf(d4.w, st[q + 3], k4.w * vi);
            }
            ypart[it][1][jg][i] = acc;
        }

        float vA = 0.f, cA = 0.f, vB = 0.f, cB = 0.f;
        if (tid < 64) {
            vA = buf[sl0][2][tid]; cA = cb[sl0];
            vB = buf[sl1][2][tid]; cB = cb[sl1];
        }

        {
            int t0 = t + 14, t1 = t + 15;
            if (t0 < TSEQ) {
                CP4(sbuf + (uint32_t)((t0 & (PF - 1)) * 1024) + mydst, lp + base0 + (size_t)t0 * CDIM + idx);
                if (tid == 0) CP4(scb + (t0 & (PF - 1)) * 4, cv + cvbase + (size_t)t0 * HNUM);
            }
            if (t1 < TSEQ) {
                CP4(sbuf + (uint32_t)((t1 & (PF - 1)) * 1024) + mydst, lp + base0 + (size_t)t1 * CDIM + idx);
                if (tid == 0) CP4(scb + (t1 & (PF - 1)) * 4, cv + cvbase + (size_t)t1 * HNUM);
            }
            CPCOMMIT();
        }
        CPWAIT5();
        __syncthreads();

        if (tid < 64) {
            float yA = ypart[it][0][0][tid] + ypart[it][0][1][tid]
                     + ypart[it][0][2][tid] + ypart[it][0][3][tid] + vA * cA;
            float yB = ypart[it][1][0][tid] + ypart[it][1][1][tid]
                     + ypart[it][1][2][tid] + ypart[it][1][3][tid] + vB * cB;
            y[base0 + (size_t)t * CDIM + tid] = yA;
            y[base0 + (size_t)(t + 1) * CDIM + tid] = yB;
        }
    }

#pragma unroll
    for (int q = 0; q < 16; q++) s_out[sbase + (size_t)q * DDIM] = st[q];
}

// ======================================================================================
// GroupNorm * g -> fp16 hi only (out GEMM is single-pass)
// ======================================================================================
__global__ void __launch_bounds__(256) gn_kernel(
    const float* __restrict__ y, const float* __restrict__ g,
    const float* __restrict__ gamma, const float* __restrict__ beta,
    __half* __restrict__ yhi)
{
    int warp = (blockIdx.x * blockDim.x + threadIdx.x) >> 5;
    int lane = threadIdx.x & 31;
    int m = warp >> 4, h = warp & 15;
    size_t base = (size_t)m * CDIM + h * DDIM;

    float2 vv = *(const float2*)&y[base + lane * 2];
    float s  = vv.x + vv.y;
    float sq = vv.x * vv.x + vv.y * vv.y;
#pragma unroll
    for (int o = 16; o > 0; o >>= 1) {
        s  += __shfl_xor_sync(0xffffffffu, s,  o);
        sq += __shfl_xor_sync(0xffffffffu, sq, o);
    }
    float mean = s * (1.f / 64.f);
    float var  = sq * (1.f / 64.f) - mean * mean;
    float inv  = rsqrtf(var + 1e-5f * (float)HNUM);

    int c0 = h * DDIM + lane * 2;
    float2 gv = *(const float2*)&g[base + lane * 2];
    float o0 = ((vv.x - mean) * inv * gamma[c0]     + beta[c0])     * gv.x;
    float o1 = ((vv.y - mean) * inv * gamma[c0 + 1] + beta[c0 + 1]) * gv.y;

    __half2 H = __halves2half2(__float2half_rn(o0), __float2half_rn(o1));
    *(uint32_t*)(yhi + base + lane * 2) = *(uint32_t*)&H;
}

// ======================================================================================
extern "C" void kernel_launch(void* const* d_in, const int* in_sizes, int n_in,
                              void* d_out, int out_size)
{
    const float* x    = (const float*)d_in[0];
    const float* xlst = (const float*)d_in[1];
    const float* s_in = (const float*)d_in[2];
    const float* miux = (const float*)d_in[3];
    const float* lam  = (const float*)d_in[4];
    const float* Aw   = (const float*)d_in[5];
    const float* Blo5 = (const float*)d_in[6];
    const float* tdm  = (const float*)d_in[7];
    const float* tdA  = (const float*)d_in[8];
    const float* tdB  = (const float*)d_in[9];
    const float* u    = (const float*)d_in[10];
    const float* Wk   = (const float*)d_in[11];
    const float* Wv   = (const float*)d_in[12];
    const float* Wr   = (const float*)d_in[13];
    const float* Wo   = (const float*)d_in[14];
    const float* Wg1  = (const float*)d_in[15];
    const float* Wg2  = (const float*)d_in[16];
    const float* gam  = (const float*)d_in[17];
    const float* bet  = (const float*)d_in[18];
    float* out = (float*)d_out;

    float *t1, *w, *dec, *kb, *vb, *rb, *gb, *yb, *cv;
    __half *xlhi, *xllo, *w0hi, *w0lo, *g0hi, *g0lo, *g1hi, *g1lo, *h1hi, *h1lo;
    __half *khi, *klo, *vhi, *vlo, *rhi, *rlo, *yhi, *Whi;
    __half *Athi, *tdAthi, *tdBthi, *G1thi, *G2thi;
    cudaGetSymbolAddress((void**)&t1,  g_t1);
    cudaGetSymbolAddress((void**)&xlhi, g_xlhi); cudaGetSymbolAddress((void**)&xllo, g_xllo);
    cudaGetSymbolAddress((void**)&w0hi, g_w0hi); cudaGetSymbolAddress((void**)&w0lo, g_w0lo);
    cudaGetSymbolAddress((void**)&g0hi, g_g0hi); cudaGetSymbolAddress((void**)&g0lo, g_g0lo);
    cudaGetSymbolAddress((void**)&g1hi, g_g1hi); cudaGetSymbolAddress((void**)&g1lo, g_g1lo);
    cudaGetSymbolAddress((void**)&h1hi, g_h1hi); cudaGetSymbolAddress((void**)&h1lo, g_h1lo);
    cudaGetSymbolAddress((void**)&khi, g_khi); cudaGetSymbolAddress((void**)&klo, g_klo);
    cudaGetSymbolAddress((void**)&vhi, g_vhi); cudaGetSymbolAddress((void**)&vlo, g_vlo);
    cudaGetSymbolAddress((void**)&rhi, g_rhi); cudaGetSymbolAddress((void**)&rlo, g_rlo);
    cudaGetSymbolAddress((void**)&yhi, g_yhi);
    cudaGetSymbolAddress((void**)&Whi, g_Whi);
    cudaGetSymbolAddress((void**)&Athi, g_Athi);
    cudaGetSymbolAddress((void**)&tdAthi, g_tdAthi);
    cudaGetSymbolAddress((void**)&tdBthi, g_tdBthi);
    cudaGetSymbolAddress((void**)&G1thi, g_G1thi);
    cudaGetSymbolAddress((void**)&G2thi, g_G2thi);
    cudaGetSymbolAddress((void**)&w,   g_w);
    cudaGetSymbolAddress((void**)&dec, g_dec);
    cudaGetSymbolAddress((void**)&kb,  g_kb);
    cudaGetSymbolAddress((void**)&vb,  g_vb);
    cudaGetSymbolAddress((void**)&rb,  g_rb);
    cudaGetSymbolAddress((void**)&gb,  g_gb);
    cudaGetSymbolAddress((void**)&yb,  g_yb);
    cudaGetSymbolAddress((void**)&cv,  g_cv);

    const size_t WSZ = (size_t)CDIM * CDIM;
    const size_t MC = (size_t)MROWS * CDIM;
    cudaFuncSetAttribute(mma_gemm16<0, 32, 1>, cudaFuncAttributeMaxDynamicSharedMemorySize, 2 * STG_A);
    cudaFuncSetAttribute(mma_gemm16<0, 32, 0>, cudaFuncAttributeMaxDynamicSharedMemorySize, 2 * STG_A);
    cudaFuncSetAttribute(mma_gemm16<0, 5, 1>,  cudaFuncAttributeMaxDynamicSharedMemorySize, 2 * STG_A);
    cudaFuncSetAttribute(mma_gemm16<2, 32, 0>, cudaFuncAttributeMaxDynamicSharedMemorySize, 2 * STG_A);
    cudaFuncSetAttribute(mma_gemm16<3, 32, 1>, cudaFuncAttributeMaxDynamicSharedMemorySize, 2 * STG_A);
    cudaFuncSetAttribute(mma_gemm16<5, 32, 0>, cudaFuncAttributeMaxDynamicSharedMemorySize, 2 * STG_A);
    cudaFuncSetAttribute(mma_gemm16<4, 2, 0>,  cudaFuncAttributeMaxDynamicSharedMemorySize, 2 * STG_A);
    cudaFuncSetAttribute(xdd_fused, cudaFuncAttributeMaxDynamicSharedMemorySize, 81920);

    dim3 thr(256);
    const int wn4 = (int)(WSZ / 4);

    // 1) xl mix -> fp16 hi/lo, x_raw passthrough
    xprep_kernel<<<(int)(MC / 4 / 256), thr>>>(
        (const float4*)x, (const float4*)xlst, miux, xlhi, xllo, (float4*)(out + MC));
    // 2) A weight transpose+pad
    tpad_h<<<(256 * CDIM + 255) / 256, thr>>>(Aw, Athi, CDIM, 160, 256);
    // 3) square-weight casts, z-batched
    {
        SplitBatch sb = { { Wk, Wv, Wr, Wo } };
        split4_kernel<<<dim3((wn4 + 255) / 256, 4), thr>>>(sb, Whi, wn4);
    }
    // 4) t1 = tanh(xl @ A)   — single-pass (LoRA path, error negligible)
    {
        GemmBatch gbat = {};
        gbat.s[0] = { xlhi, xllo, Athi, t1, nullptr };
        mma_gemm16<2, 32, 0><<<dim3(2, MROWS / 128, 1), thr, 2 * STG_A>>>(gbat, CDIM, nullptr, nullptr);
    }

    // 5-6) decay-LoRA weight preps
    tpad_h<<<(128 * CDIM + 255) / 256, thr>>>(tdA, tdAthi, CDIM, 64, 128);
    tpad_h<<<(CDIM * 64 + 255) / 256, thr>>>(tdB, tdBthi, 64, CDIM, CDIM);

    // 7) fused xdd
    xdd_fused<<<dim3(CDIM / 64, MROWS / 64), thr, 81920>>>(
        t1, Blo5, x, xlst, lam, w0hi, w0lo, g0hi, g0lo, khi, klo, vhi, vlo, rhi, rlo);

    // 8) h1 = tanh(w0 @ td_A) — single-pass (LoRA delta small vs tdm)
    {
        GemmBatch gbat = {};
        gbat.s[0] = { w0hi, w0lo, tdAthi, nullptr, nullptr };
        mma_gemm16<5, 32, 0><<<dim3(1, MROWS / 128, 1), thr, 2 * STG_A>>>(gbat, CDIM, h1hi, h1lo);
    }
    // 9) w = tdm + h1 @ td_B ; dec = exp(-exp(w)) — single-pass
    {
        GemmBatch gbat = {};
        gbat.s[0] = { h1hi, h1lo, tdBthi, w, tdm };
        mma_gemm16<4, 2, 0><<<dim3(CDIM / 128, MROWS / 128, 1), thr, 2 * STG_A>>>(gbat, 64, (__half*)dec, nullptr);
    }

    // 10) k/v/r projections, z-batched (2-pass: precision critical)
    {
        GemmBatch gbat = {};
        gbat.s[0] = { khi, klo, Whi + 0 * WSZ, kb, w };
        gbat.s[1] = { vhi, vlo, Whi + 1 * WSZ, vb, nullptr };
        gbat.s[2] = { rhi, rlo, Whi + 2 * WSZ, rb, nullptr };
        mma_gemm16<0, 32, 1><<<dim3(CDIM / 128, MROWS / 128, 3), thr, 2 * STG_A>>>(gbat, CDIM, nullptr, nullptr);
    }

    // 11-12) gate weight preps
    tpad_h<<<(256 * CDIM + 255) / 256, thr>>>(Wg1, G1thi, CDIM, 160, 256);
    tpad_h<<<(CDIM * 160 + 255) / 256, thr>>>(Wg2, G2thi, 160, CDIM, CDIM);

    // 13) g1 = tanh(g0 @ W_g1) -> fp16 hi/lo (2-pass: gate multiplies out)
    {
        GemmBatch gbat = {};
        gbat.s[0] = { g0hi, g0lo, G1thi, nullptr, nullptr };
        mma_gemm16<3, 32, 1><<<dim3(2, MROWS / 128, 1), thr, 2 * STG_A>>>(gbat, CDIM, g1hi, g1lo);
    }
    // 14) g = g1 @ W_g2   (K=160, 2-pass)
    {
        GemmBatch gbat = {};
        gbat.s[0] = { g1hi, g1lo, G2thi, gb, nullptr };
        mma_gemm16<0, 5, 1><<<dim3(CDIM / 128, MROWS / 128, 1), thr, 2 * STG_A>>>(gbat, 160, nullptr, nullptr);
    }

    // 15) cvec precompute
    cvec_kernel<<<(MROWS * HNUM) / 8, thr>>>(rb, kb, u, cv);

    // 16) WKV-6 scan (PF=16 ring, 2 steps/barrier)
    wkv_kernel<<<BSZ * HNUM, thr>>>(rb, kb, vb, dec, cv, s_in, yb, out + 2 * MC);

    // 17) GroupNorm * g -> fp16 hi only
    gn_kernel<<<(MROWS * HNUM) / 8, thr>>>(yb, gb, gam, bet, yhi);

    // 18) out = (yn*g) @ Wo^T — single-pass (normalized O(1) activations)
    {
        GemmBatch gbat = {};
        gbat.s[0] = { yhi, yhi, Whi + 3 * WSZ, out, nullptr };
        mma_gemm16<0, 32, 0><<<dim3(CDIM / 128, MROWS / 128, 1), thr, 2 * STG_A>>>(gbat, CDIM, nullptr, nullptr);
    }
}

// round 15
// speedup vs baseline: 1.3757x; 1.1204x over previous
#include <cuda_runtime.h>
#include <cuda_fp16.h>
#include <stdint.h>
#include <math.h>

#define MROWS 16384   // B*T = 8*2048
#define CDIM  1024
#define HNUM  16
#define DDIM  64
#define TSEQ  2048
#define BSZ   8

// ---------------- scratch (static device memory; no runtime allocation) ----------------
__device__ float g_t1 [(size_t)MROWS * 160];
__device__ __half g_xlhi[(size_t)MROWS * CDIM], g_xllo[(size_t)MROWS * CDIM];
__device__ __half g_w0hi[(size_t)MROWS * CDIM], g_w0lo[(size_t)MROWS * CDIM];
__device__ __half g_g0hi[(size_t)MROWS * CDIM], g_g0lo[(size_t)MROWS * CDIM];
__device__ __half g_g1hi[(size_t)MROWS * 160],  g_g1lo[(size_t)MROWS * 160];
__device__ __half g_h1hi[(size_t)MROWS * 64],   g_h1lo[(size_t)MROWS * 64];
__device__ __half g_khi[(size_t)MROWS * CDIM];
__device__ __half g_vhi[(size_t)MROWS * CDIM];
__device__ __half g_rhi[(size_t)MROWS * CDIM];
__device__ __half g_yhi[(size_t)MROWS * CDIM];
__device__ __half g_Whi[4][(size_t)CDIM * CDIM];
__device__ __half g_Athi[(size_t)256 * CDIM];
__device__ __half g_tdAthi[(size_t)128 * CDIM];
__device__ __half g_tdBthi[(size_t)CDIM * 64];
__device__ __half g_G1thi[(size_t)256 * CDIM];
__device__ __half g_G2thi[(size_t)CDIM * 160];
__device__ float g_w  [(size_t)MROWS * CDIM];
__device__ float g_dec[(size_t)MROWS * CDIM];
__device__ float g_kb [(size_t)MROWS * CDIM];
__device__ float g_vb [(size_t)MROWS * CDIM];
__device__ float g_rb [(size_t)MROWS * CDIM];
__device__ float g_gb [(size_t)MROWS * CDIM];
__device__ float g_yb [(size_t)MROWS * CDIM];
__device__ float g_cv [(size_t)MROWS * HNUM];

// ======================================================================================
// helpers
// ======================================================================================
__device__ __forceinline__ uint32_t smem_u32(const void* p) {
    uint32_t a;
    asm("{ .reg .u64 t; cvta.to.shared.u64 t, %1; cvt.u32.u64 %0, t; }" : "=r"(a) : "l"(p));
    return a;
}
__device__ __forceinline__ void ldsm4(uint32_t* r, uint32_t addr) {
    asm volatile("ldmatrix.sync.aligned.m8n8.x4.shared.b16 {%0,%1,%2,%3}, [%4];"
        : "=r"(r[0]), "=r"(r[1]), "=r"(r[2]), "=r"(r[3]) : "r"(addr));
}
__device__ __forceinline__ void mma16816(float* c, const uint32_t* a, const uint32_t* b) {
    asm volatile("mma.sync.aligned.m16n8k16.row.col.f32.f16.f16.f32 "
        "{%0,%1,%2,%3}, {%4,%5,%6,%7}, {%8,%9}, {%0,%1,%2,%3};"
        : "+f"(c[0]), "+f"(c[1]), "+f"(c[2]), "+f"(c[3])
        : "r"(a[0]), "r"(a[1]), "r"(a[2]), "r"(a[3]), "r"(b[0]), "r"(b[1]));
}
#define CP16(d, s) asm volatile("cp.async.cg.shared.global [%0], [%1], 16;" :: "r"(d), "l"(s))
#define CP4(d, s)  asm volatile("cp.async.ca.shared.global [%0], [%1], 4;"  :: "r"(d), "l"(s))
#define CPCOMMIT() asm volatile("cp.async.commit_group;" ::: "memory")
#define CPWAIT1()  asm volatile("cp.async.wait_group 1;" ::: "memory")
#define CPWAIT5()  asm volatile("cp.async.wait_group 5;" ::: "memory")

__device__ __forceinline__ void cvt_hilo4h(float4 v, uint2& hi, uint2& lo) {
    __half h0 = __float2half_rn(v.x), h1 = __float2half_rn(v.y);
    __half h2 = __float2half_rn(v.z), h3 = __float2half_rn(v.w);
    __half l0 = __float2half_rn(v.x - __half2float(h0));
    __half l1 = __float2half_rn(v.y - __half2float(h1));
    __half l2 = __float2half_rn(v.z - __half2float(h2));
    __half l3 = __float2half_rn(v.w - __half2float(h3));
    __half2 H01 = __halves2half2(h0, h1), H23 = __halves2half2(h2, h3);
    __half2 L01 = __halves2half2(l0, l1), L23 = __halves2half2(l2, l3);
    hi = make_uint2(*(uint32_t*)&H01, *(uint32_t*)&H23);
    lo = make_uint2(*(uint32_t*)&L01, *(uint32_t*)&L23);
}
__device__ __forceinline__ uint2 cvt_hi4(float4 v) {
    __half2 H01 = __halves2half2(__float2half_rn(v.x), __float2half_rn(v.y));
    __half2 H23 = __halves2half2(__float2half_rn(v.z), __float2half_rn(v.w));
    return make_uint2(*(uint32_t*)&H01, *(uint32_t*)&H23);
}

// ======================================================================================
// prep kernels
// ======================================================================================
struct SplitBatch { const float* src[4]; };

__global__ void __launch_bounds__(256) split4_kernel(
    SplitBatch sb, __half* __restrict__ hi, int n4)
{
    int idx = blockIdx.x * 256 + threadIdx.x;
    if (idx >= n4) return;
    const size_t zoff = (size_t)blockIdx.y * CDIM * CDIM;
    *(uint2*)(hi + zoff + (size_t)idx * 4) = cvt_hi4(((const float4*)sb.src[blockIdx.y])[idx]);
}

__global__ void __launch_bounds__(256) tpad_h(
    const float* __restrict__ in, __half* __restrict__ ohi, int K, int N, int Npad)
{
    int t = blockIdx.x * 256 + threadIdx.x;
    if (t >= Npad * K) return;
    int n = t / K, k = t - n * K;
    float v = (n < N) ? in[(size_t)k * N + n] : 0.f;
    ohi[t] = __float2half_rn(v);
}

__global__ void __launch_bounds__(256) xprep_kernel(
    const float4* __restrict__ x, const float4* __restrict__ xl,
    const float* __restrict__ miux,
    __half* __restrict__ xhi, __half* __restrict__ xlo,
    float4* __restrict__ xraw)
{
    int idx = blockIdx.x * 256 + threadIdx.x;   // MC/4 total
    float4 xv = x[idx], xlv = xl[idx];
    float4 mv = *(const float4*)(miux + (idx & 255) * 4);
    float4 o;
    o.x = fmaf(xlv.x - xv.x, mv.x, xv.x);
    o.y = fmaf(xlv.y - xv.y, mv.y, xv.y);
    o.z = fmaf(xlv.z - xv.z, mv.z, xv.z);
    o.w = fmaf(xlv.w - xv.w, mv.w, xv.w);
    uint2 h, l;
    cvt_hilo4h(o, h, l);
    *(uint2*)(xhi + (size_t)idx * 4) = h;
    *(uint2*)(xlo + (size_t)idx * 4) = l;
    xraw[idx] = xv;
}

// ======================================================================================
// fp16 HMMA GEMM: C[m,n] = sum_k (Ahi [+ Alo if TWO])[m,k] * Bhi[n,k]
// Tile 128x128, BK=32, KCH chunks, stride kst, 2-stage cp.async, f32 acc.
// EPI 0: fp32 stride CDIM (+exp(min(w,0)) if wptr); 2: tanh fp32 s160;
// 3: tanh fp16 hi/lo s160; 5: tanh fp16 hi/lo s64; 4: +wptr[n], fp32 + exp(-exp())
// ======================================================================================
#define STG_A 30720
#define OAL3  10240
#define OBH3  20480

struct GemmSet {
    const __half *ahi, *alo, *bhi;
    float* c;
    const float* wptr;
};
struct GemmBatch { GemmSet s[3]; };

template <int EPI, int KCH, int TWO>
__global__ void __launch_bounds__(256, 2) mma_gemm16(
    GemmBatch gbat, int kst, __half* __restrict__ chi, __half* __restrict__ clo)
{
    const GemmSet gs = gbat.s[blockIdx.z];
    extern __shared__ char smem[];
    const int tid = threadIdx.x, wid = tid >> 5, lane = tid & 31;
    const int bm = blockIdx.y, bn = blockIdx.x;
    const uint32_t sbase = smem_u32(smem);

    const int row = tid >> 1, half = tid & 1;
    const __half* pAhi = gs.ahi + (size_t)(bm * 128 + row) * kst + half * 16;
    const __half* pAlo = TWO ? gs.alo + (size_t)(bm * 128 + row) * kst + half * 16 : nullptr;
    const __half* pBhi = gs.bhi + (size_t)(bn * 128 + row) * kst + half * 16;
    const uint32_t dA = (uint32_t)(row * 80 + half * 32);

    auto issue = [&](int s, int k0) {
        uint32_t sb2 = sbase + s * STG_A;
        CP16(sb2 + dA,             pAhi + k0); CP16(sb2 + dA + 16,        pAhi + k0 + 8);
        if (TWO) {
            CP16(sb2 + OAL3 + dA,      pAlo + k0);
            CP16(sb2 + OAL3 + dA + 16, pAlo + k0 + 8);
        }
        CP16(sb2 + OBH3 + dA,      pBhi + k0); CP16(sb2 + OBH3 + dA + 16, pBhi + k0 + 8);
    };

    float acc[2][8][4];
#pragma unroll
    for (int a = 0; a < 2; a++)
#pragma unroll
        for (int b = 0; b < 8; b++)
#pragma unroll
            for (int c = 0; c < 4; c++) acc[a][b][c] = 0.f;

    const int arow = (wid & 3) * 32 + (lane & 7) + ((lane >> 3) & 1) * 8;
    const int acol8 = (lane >> 4) * 8;
    const int brow = (wid >> 2) * 64 + ((lane >> 4) << 3) + (lane & 7);
    const int bcol8 = ((lane >> 3) & 1) * 8;

    issue(0, 0);  CPCOMMIT();
    if (KCH > 1) issue(1, 32);
    CPCOMMIT();

    for (int c = 0; c < KCH; c++) {
        CPWAIT1();
        __syncthreads();
        const uint32_t sA = sbase + (c & 1) * STG_A;
#pragma unroll
        for (int ks = 0; ks < 2; ks++) {
            const int kc = ks * 16;
            uint32_t ah[2][4], al[2][4], bh[4][4];
#pragma unroll
            for (int mt = 0; mt < 2; mt++) {
                uint32_t off = (uint32_t)((arow + mt * 16) * 40 + kc + acol8) * 2;
                ldsm4(ah[mt], sA + off);
                if (TWO) ldsm4(al[mt], sA + OAL3 + off);
            }
#pragma unroll
            for (int nt2 = 0; nt2 < 4; nt2++) {
                uint32_t boff = (uint32_t)((brow + nt2 * 16) * 40 + kc + bcol8) * 2;
                ldsm4(bh[nt2], sA + OBH3 + boff);
            }
#pragma unroll
            for (int nt2 = 0; nt2 < 4; nt2++)
#pragma unroll
                for (int mt = 0; mt < 2; mt++) {
                    mma16816(acc[mt][nt2 * 2],     ah[mt], bh[nt2]);
                    mma16816(acc[mt][nt2 * 2 + 1], ah[mt], bh[nt2] + 2);
                }
            if (TWO) {
#pragma unroll
                for (int nt2 = 0; nt2 < 4; nt2++)
#pragma unroll
                    for (int mt = 0; mt < 2; mt++) {
                        mma16816(acc[mt][nt2 * 2],     al[mt], bh[nt2]);
                        mma16816(acc[mt][nt2 * 2 + 1], al[mt], bh[nt2] + 2);
                    }
            }
        }
        __syncthreads();
        {
            int cn = c + 2;
            if (cn < KCH) issue(cn & 1, cn * 32);
            CPCOMMIT();
        }
    }

    // epilogue
#pragma unroll
    for (int mt = 0; mt < 2; mt++) {
        const int m = bm * 128 + (wid & 3) * 32 + mt * 16 + (lane >> 2);
#pragma unroll
        for (int nt = 0; nt < 8; nt++) {
            const int n = bn * 128 + (wid >> 2) * 64 + nt * 8 + (lane & 3) * 2;
            float c0 = acc[mt][nt][0], c1 = acc[mt][nt][1];
            float c2 = acc[mt][nt][2], c3 = acc[mt][nt][3];
            if (EPI == 0) {
                size_t i0 = (size_t)m * CDIM + n;
                size_t i1 = i0 + (size_t)8 * CDIM;
                if (gs.wptr) {
                    float2 wa = *(const float2*)(gs.wptr + i0);
                    float2 wb = *(const float2*)(gs.wptr + i1);
                    c0 *= __expf(fminf(wa.x, 0.f)); c1 *= __expf(fminf(wa.y, 0.f));
                    c2 *= __expf(fminf(wb.x, 0.f)); c3 *= __expf(fminf(wb.y, 0.f));
                }
                *(float2*)(gs.c + i0) = make_float2(c0, c1);
                *(float2*)(gs.c + i1) = make_float2(c2, c3);
            } else if (EPI == 4) {
                size_t i0 = (size_t)m * CDIM + n;
                size_t i1 = i0 + (size_t)8 * CDIM;
                c0 += gs.wptr[n];     c1 += gs.wptr[n + 1];
                c2 += gs.wptr[n];     c3 += gs.wptr[n + 1];
                float* dec = (float*)chi;
                *(float2*)(gs.c + i0) = make_float2(c0, c1);
                *(float2*)(gs.c + i1) = make_float2(c2, c3);
                *(float2*)(dec + i0) = make_float2(__expf(-__expf(c0)), __expf(-__expf(c1)));
                *(float2*)(dec + i1) = make_float2(__expf(-__expf(c2)), __expf(-__expf(c3)));
            } else {
                const int NS = (EPI == 5) ? 64 : 160;
                if (n >= NS) continue;
                c0 = tanhf(c0); c1 = tanhf(c1); c2 = tanhf(c2); c3 = tanhf(c3);
                size_t i0 = (size_t)m * NS + n;
                size_t i1 = i0 + (size_t)8 * NS;
                if (EPI == 2) {
                    *(float2*)(gs.c + i0) = make_float2(c0, c1);
                    *(float2*)(gs.c + i1) = make_float2(c2, c3);
                } else {
                    __half h0 = __float2half_rn(c0), h1 = __float2half_rn(c1);
                    __half h2 = __float2half_rn(c2), h3 = __float2half_rn(c3);
                    __half l0 = __float2half_rn(c0 - __half2float(h0));
                    __half l1 = __float2half_rn(c1 - __half2float(h1));
                    __half l2 = __float2half_rn(c2 - __half2float(h2));
                    __half l3 = __float2half_rn(c3 - __half2float(h3));
                    __half2 H01 = __halves2half2(h0, h1), H23 = __halves2half2(h2, h3);
                    __half2 L01 = __halves2half2(l0, l1), L23 = __halves2half2(l2, l3);
                    *(uint32_t*)(chi + i0) = *(uint32_t*)&H01;
                    *(uint32_t*)(chi + i1) = *(uint32_t*)&H23;
                    *(uint32_t*)(clo + i0) = *(uint32_t*)&L01;
                    *(uint32_t*)(clo + i1) = *(uint32_t*)&L23;
                }
            }
        }
    }
}

// ======================================================================================
// fused xdd (K=32 LoRA): w0/g0 -> fp16 hi/lo ; k/v/r -> fp16 hi only
// ======================================================================================
__global__ void __launch_bounds__(256) xdd_fused(
    const float* __restrict__ t1, const float* __restrict__ Blo5,
    const float* __restrict__ x, const float* __restrict__ xl,
    const float* __restrict__ lam,
    __half* __restrict__ w0hi, __half* __restrict__ w0lo,
    __half* __restrict__ g0hi, __half* __restrict__ g0lo,
    __half* __restrict__ khi, __half* __restrict__ vhi, __half* __restrict__ rhi)
{
    extern __shared__ float sh[];
    float* T1 = sh;              // [5][64][32]
    float* BL = sh + 10240;      // [5][32][64]
    const int tid = threadIdx.x;
    const int bm = blockIdx.y, bn = blockIdx.x;
    const int tx = tid & 15, ty = tid >> 4;

#pragma unroll
    for (int ii = 0; ii < 10; ii++) {
        int c4 = tid + ii * 256;
        int f = c4 >> 9, rem = c4 & 511;
        int row = rem >> 3, kq = rem & 7;
        float4 v = *(const float4*)(t1 + (size_t)f * MROWS * 32 + (size_t)(bm * 64 + row) * 32 + kq * 4);
        *(float4*)&T1[(f * 64 + row) * 32 + kq * 4] = v;
    }
#pragma unroll
    for (int ii = 0; ii < 10; ii++) {
        int c4 = tid + ii * 256;
        int f = c4 >> 9, rem = c4 & 511;
        int k = rem >> 4, cq = rem & 15;
        float4 v = *(const float4*)(Blo5 + (size_t)f * 32 * CDIM + (size_t)k * CDIM + bn * 64 + cq * 4);
        *(float4*)&BL[(f * 32 + k) * 64 + cq * 4] = v;
    }
    __syncthreads();

    float acc[5][4][4];
#pragma unroll
    for (int f = 0; f < 5; f++)
#pragma unroll
        for (int i = 0; i < 4; i++)
#pragma unroll
            for (int j = 0; j < 4; j++) acc[f][i][j] = 0.f;

    for (int k = 0; k < 32; k++) {
#pragma unroll
        for (int f = 0; f < 5; f++) {
            float4 b = *(const float4*)&BL[(f * 32 + k) * 64 + tx * 4];
            float a0 = T1[(f * 64 + ty * 4 + 0) * 32 + k];
            float a1 = T1[(f * 64 + ty * 4 + 1) * 32 + k];
            float a2 = T1[(f * 64 + ty * 4 + 2) * 32 + k];
            float a3 = T1[(f * 64 + ty * 4 + 3) * 32 + k];
            acc[f][0][0] = fmaf(a0, b.x, acc[f][0][0]); acc[f][0][1] = fmaf(a0, b.y, acc[f][0][1]);
            acc[f][0][2] = fmaf(a0, b.z, acc[f][0][2]); acc[f][0][3] = fmaf(a0, b.w, acc[f][0][3]);
            acc[f][1][0] = fmaf(a1, b.x, acc[f][1][0]); acc[f][1][1] = fmaf(a1, b.y, acc[f][1][1]);
            acc[f][1][2] = fmaf(a1, b.z, acc[f][1][2]); acc[f][1][3] = fmaf(a1, b.w, acc[f][1][3]);
            acc[f][2][0] = fmaf(a2, b.x, acc[f][2][0]); acc[f][2][1] = fmaf(a2, b.y, acc[f][2][1]);
            acc[f][2][2] = fmaf(a2, b.z, acc[f][2][2]); acc[f][2][3] = fmaf(a2, b.w, acc[f][2][3]);
            acc[f][3][0] = fmaf(a3, b.x, acc[f][3][0]); acc[f][3][1] = fmaf(a3, b.y, acc[f][3][1]);
            acc[f][3][2] = fmaf(a3, b.z, acc[f][3][2]); acc[f][3][3] = fmaf(a3, b.w, acc[f][3][3]);
        }
    }

    const int n0 = bn * 64 + tx * 4;
    float4 lamv[5];
#pragma unroll
    for (int f = 0; f < 5; f++) lamv[f] = *(const float4*)(lam + f * CDIM + n0);

#pragma unroll
    for (int i = 0; i < 4; i++) {
        const int m = bm * 64 + ty * 4 + i;
        size_t ix = (size_t)m * CDIM + n0;
        float4 xv = *(const float4*)(x + ix);
        float4 xlv = *(const float4*)(xl + ix);
        float4 ba = make_float4(xlv.x - xv.x, xlv.y - xv.y, xlv.z - xv.z, xlv.w - xv.w);
        float4 o[5];
#pragma unroll
        for (int f = 0; f < 5; f++) {
            o[f].x = fmaf(ba.x, lamv[f].x + acc[f][i][0], xv.x);
            o[f].y = fmaf(ba.y, lamv[f].y + acc[f][i][1], xv.y);
            o[f].z = fmaf(ba.z, lamv[f].z + acc[f][i][2], xv.z);
            o[f].w = fmaf(ba.w, lamv[f].w + acc[f][i][3], xv.w);
        }
        uint2 h, l;
        cvt_hilo4h(o[0], h, l); *(uint2*)(w0hi + ix) = h; *(uint2*)(w0lo + ix) = l;
        *(uint2*)(khi + ix) = cvt_hi4(o[1]);
        *(uint2*)(vhi + ix) = cvt_hi4(o[2]);
        *(uint2*)(rhi + ix) = cvt_hi4(o[3]);
        cvt_hilo4h(o[4], h, l); *(uint2*)(g0hi + ix) = h; *(uint2*)(g0lo + ix) = l;
    }
}

// ======================================================================================
// cvec[m,h] = sum_j r*u*k
// ======================================================================================
__global__ void __launch_bounds__(256) cvec_kernel(
    const float* __restrict__ rb, const float* __restrict__ kb,
    const float* __restrict__ u, float* __restrict__ cv)
{
    int gw = (blockIdx.x * 256 + threadIdx.x) >> 5;
    int lane = threadIdx.x & 31;
    int m = gw >> 4, h = gw & 15;
    size_t base = (size_t)m * CDIM + h * DDIM;
    float p = rb[base + lane] * u[h * DDIM + lane] * kb[base + lane]
            + rb[base + 32 + lane] * u[h * DDIM + 32 + lane] * kb[base + 32 + lane];
#pragma unroll
    for (int o = 16; o > 0; o >>= 1) p += __shfl_xor_sync(0xffffffffu, p, o);
    if (lane == 0) cv[(size_t)m * HNUM + h] = p;
}

// ======================================================================================
// WKV-6 scan — 256 threads, PF=16 cp.async ring, TWO steps per barrier
// ======================================================================================
#define PF 16
__global__ void __launch_bounds__(256) wkv_kernel(
    const float* __restrict__ r, const float* __restrict__ k,
    const float* __restrict__ v, const float* __restrict__ dec,
    const float* __restrict__ cv, const float* __restrict__ s_in,
    float* __restrict__ y, float* __restrict__ s_out)
{
    const int bh = blockIdx.x;
    const int b = bh >> 4, h = bh & 15;
    const int tid = threadIdx.x;
    const int i  = tid & 63;
    const int jg = tid >> 6;
    const int j0 = jg * 16;

    __shared__ float buf[PF][4][64];
    __shared__ float cb[PF];
    __shared__ float ypart[2][2][4][64];

    float st[16];
    size_t sbase = (((size_t)b * HNUM + h) * DDIM + j0) * DDIM + i;
#pragma unroll
    for (int q = 0; q < 16; q++) st[q] = s_in[sbase + (size_t)q * DDIM];

    const int arr = tid >> 6, idx = tid & 63;
    const float* lp = (arr == 0) ? r : (arr == 1) ? k : (arr == 2) ? v : dec;
    const size_t base0 = ((size_t)b * TSEQ) * CDIM + h * DDIM;
    const size_t cvbase = (size_t)(b * TSEQ) * HNUM + h;

    const uint32_t sbuf = smem_u32(&buf[0][0][0]);
    const uint32_t scb  = smem_u32(&cb[0]);
    const uint32_t mydst = (uint32_t)((arr * 64 + idx) * 4);

    for (int p = 0; p < 7; p++) {
        CP4(sbuf + (uint32_t)((2 * p) * 1024) + mydst,     lp + base0 + (size_t)(2 * p) * CDIM + idx);
        CP4(sbuf + (uint32_t)((2 * p + 1) * 1024) + mydst, lp + base0 + (size_t)(2 * p + 1) * CDIM + idx);
        if (tid == 0) {
            CP4(scb + (2 * p) * 4,     cv + cvbase + (size_t)(2 * p) * HNUM);
            CP4(scb + (2 * p + 1) * 4, cv + cvbase + (size_t)(2 * p + 1) * HNUM);
        }
        CPCOMMIT();
    }
    CPWAIT5();
    __syncthreads();

    for (int t = 0; t < TSEQ; t += 2) {
        const int it = (t >> 1) & 1;
        const int sl0 = t & (PF - 1), sl1 = (t + 1) & (PF - 1);

        {
            const float vi = buf[sl0][2][i];
            float acc = 0.f;
#pragma unroll
            for (int q = 0; q < 16; q += 4) {
                float4 r4 = *(const float4*)&buf[sl0][0][j0 + q];
                float4 k4 = *(const float4*)&buf[sl0][1][j0 + q];
                float4 d4 = *(const float4*)&buf[sl0][3][j0 + q];
                acc = fmaf(r4.x, st[q + 0], acc); st[q + 0] = fmaf(d4.x, st[q + 0], k4.x * vi);
                acc = fmaf(r4.y, st[q + 1], acc); st[q + 1] = fmaf(d4.y, st[q + 1], k4.y * vi);
                acc = fmaf(r4.z, st[q + 2], acc); st[q + 2] = fmaf(d4.z, st[q + 2], k4.z * vi);
                acc = fmaf(r4.w, st[q + 3], acc); st[q + 3] = fmaf(d4.w, st[q + 3], k4.w * vi);
            }
            ypart[it][0][jg][i] = acc;
        }
        {
            const float vi = buf[sl1][2][i];
            float acc = 0.f;
#pragma unroll
            for (int q = 0; q < 16; q += 4) {
                float4 r4 = *(const float4*)&buf[sl1][0][j0 + q];
                float4 k4 = *(const float4*)&buf[sl1][1][j0 + q];
                float4 d4 = *(const float4*)&buf[sl1][3][j0 + q];
                acc = fmaf(r4.x, st[q + 0], acc); st[q + 0] = fmaf(d4.x, st[q + 0], k4.x * vi);
                acc = fmaf(r4.y, st[q + 1], acc); st[q + 1] = fmaf(d4.y, st[q + 1], k4.y * vi);
                acc = fmaf(r4.z, st[q + 2], acc); st[q + 2] = fmaf(d4.z, st[q + 2], k4.z * vi);
                acc = fmaf(r4.w, st[q + 3], acc); st[q + 3] = fmaf(d4.w, st[q + 3], k4.w * vi);
            }
            ypart[it][1][jg][i] = acc;
        }

        float vA = 0.f, cA = 0.f, vB = 0.f, cB = 0.f;
        if (tid < 64) {
            vA = buf[sl0][2][tid]; cA = cb[sl0];
            vB = buf[sl1][2][tid]; cB = cb[sl1];
        }

        {
            int t0 = t + 14, t1 = t + 15;
            if (t0 < TSEQ) {
                CP4(sbuf + (uint32_t)((t0 & (PF - 1)) * 1024) + mydst, lp + base0 + (size_t)t0 * CDIM + idx);
                if (tid == 0) CP4(scb + (t0 & (PF - 1)) * 4, cv + cvbase + (size_t)t0 * HNUM);
            }
            if (t1 < TSEQ) {
                CP4(sbuf + (uint32_t)((t1 & (PF - 1)) * 1024) + mydst, lp + base0 + (size_t)t1 * CDIM + idx);
                if (tid == 0) CP4(scb + (t1 & (PF - 1)) * 4, cv + cvbase + (size_t)t1 * HNUM);
            }
            CPCOMMIT();
        }
        CPWAIT5();
        __syncthreads();

        if (tid < 64) {
            float yA = ypart[it][0][0][tid] + ypart[it][0][1][tid]
                     + ypart[it][0][2][tid] + ypart[it][0][3][tid] + vA * cA;
            float yB = ypart[it][1][0][tid] + ypart[it][1][1][tid]
                     + ypart[it][1][2][tid] + ypart[it][1][3][tid] + vB * cB;
            y[base0 + (size_t)t * CDIM + tid] = yA;
            y[base0 + (size_t)(t + 1) * CDIM + tid] = yB;
        }
    }

#pragma unroll
    for (int q = 0; q < 16; q++) s_out[sbase + (size_t)q * DDIM] = st[q];
}

// ======================================================================================
// GroupNorm * g -> fp16 hi only
// ======================================================================================
__global__ void __launch_bounds__(256) gn_kernel(
    const float* __restrict__ y, const float* __restrict__ g,
    const float* __restrict__ gamma, const float* __restrict__ beta,
    __half* __restrict__ yhi)
{
    int warp = (blockIdx.x * blockDim.x + threadIdx.x) >> 5;
    int lane = threadIdx.x & 31;
    int m = warp >> 4, h = warp & 15;
    size_t base = (size_t)m * CDIM + h * DDIM;

    float2 vv = *(const float2*)&y[base + lane * 2];
    float s  = vv.x + vv.y;
    float sq = vv.x * vv.x + vv.y * vv.y;
#pragma unroll
    for (int o = 16; o > 0; o >>= 1) {
        s  += __shfl_xor_sync(0xffffffffu, s,  o);
        sq += __shfl_xor_sync(0xffffffffu, sq, o);
    }
    float mean = s * (1.f / 64.f);
    float var  = sq * (1.f / 64.f) - mean * mean;
    float inv  = rsqrtf(var + 1e-5f * (float)HNUM);

    int c0 = h * DDIM + lane * 2;
    float2 gv = *(const float2*)&g[base + lane * 2];
    float o0 = ((vv.x - mean) * inv * gamma[c0]     + beta[c0])     * gv.x;
    float o1 = ((vv.y - mean) * inv * gamma[c0 + 1] + beta[c0 + 1]) * gv.y;

    __half2 H = __halves2half2(__float2half_rn(o0), __float2half_rn(o1));
    *(uint32_t*)(yhi + base + lane * 2) = *(uint32_t*)&H;
}

// ======================================================================================
extern "C" void kernel_launch(void* const* d_in, const int* in_sizes, int n_in,
                              void* d_out, int out_size)
{
    const float* x    = (const float*)d_in[0];
    const float* xlst = (const float*)d_in[1];
    const float* s_in = (const float*)d_in[2];
    const float* miux = (const float*)d_in[3];
    const float* lam  = (const float*)d_in[4];
    const float* Aw   = (const float*)d_in[5];
    const float* Blo5 = (const float*)d_in[6];
    const float* tdm  = (const float*)d_in[7];
    const float* tdA  = (const float*)d_in[8];
    const float* tdB  = (const float*)d_in[9];
    const float* u    = (const float*)d_in[10];
    const float* Wk   = (const float*)d_in[11];
    const float* Wv   = (const float*)d_in[12];
    const float* Wr   = (const float*)d_in[13];
    const float* Wo   = (const float*)d_in[14];
    const float* Wg1  = (const float*)d_in[15];
    const float* Wg2  = (const float*)d_in[16];
    const float* gam  = (const float*)d_in[17];
    const float* bet  = (const float*)d_in[18];
    float* out = (float*)d_out;

    float *t1, *w, *dec, *kb, *vb, *rb, *gb, *yb, *cv;
    __half *xlhi, *xllo, *w0hi, *w0lo, *g0hi, *g0lo, *g1hi, *g1lo, *h1hi, *h1lo;
    __half *khi, *vhi, *rhi, *yhi, *Whi;
    __half *Athi, *tdAthi, *tdBthi, *G1thi, *G2thi;
    cudaGetSymbolAddress((void**)&t1,  g_t1);
    cudaGetSymbolAddress((void**)&xlhi, g_xlhi); cudaGetSymbolAddress((void**)&xllo, g_xllo);
    cudaGetSymbolAddress((void**)&w0hi, g_w0hi); cudaGetSymbolAddress((void**)&w0lo, g_w0lo);
    cudaGetSymbolAddress((void**)&g0hi, g_g0hi); cudaGetSymbolAddress((void**)&g0lo, g_g0lo);
    cudaGetSymbolAddress((void**)&g1hi, g_g1hi); cudaGetSymbolAddress((void**)&g1lo, g_g1lo);
    cudaGetSymbolAddress((void**)&h1hi, g_h1hi); cudaGetSymbolAddress((void**)&h1lo, g_h1lo);
    cudaGetSymbolAddress((void**)&khi, g_khi);
    cudaGetSymbolAddress((void**)&vhi, g_vhi);
    cudaGetSymbolAddress((void**)&rhi, g_rhi);
    cudaGetSymbolAddress((void**)&yhi, g_yhi);
    cudaGetSymbolAddress((void**)&Whi, g_Whi);
    cudaGetSymbolAddress((void**)&Athi, g_Athi);
    cudaGetSymbolAddress((void**)&tdAthi, g_tdAthi);
    cudaGetSymbolAddress((void**)&tdBthi, g_tdBthi);
    cudaGetSymbolAddress((void**)&G1thi, g_G1thi);
    cudaGetSymbolAddress((void**)&G2thi, g_G2thi);
    cudaGetSymbolAddress((void**)&w,   g_w);
    cudaGetSymbolAddress((void**)&dec, g_dec);
    cudaGetSymbolAddress((void**)&kb,  g_kb);
    cudaGetSymbolAddress((void**)&vb,  g_vb);
    cudaGetSymbolAddress((void**)&rb,  g_rb);
    cudaGetSymbolAddress((void**)&gb,  g_gb);
    cudaGetSymbolAddress((void**)&yb,  g_yb);
    cudaGetSymbolAddress((void**)&cv,  g_cv);

    const size_t WSZ = (size_t)CDIM * CDIM;
    const size_t MC = (size_t)MROWS * CDIM;
    cudaFuncSetAttribute(mma_gemm16<0, 32, 1>, cudaFuncAttributeMaxDynamicSharedMemorySize, 2 * STG_A);
    cudaFuncSetAttribute(mma_gemm16<0, 32, 0>, cudaFuncAttributeMaxDynamicSharedMemorySize, 2 * STG_A);
    cudaFuncSetAttribute(mma_gemm16<0, 5, 1>,  cudaFuncAttributeMaxDynamicSharedMemorySize, 2 * STG_A);
    cudaFuncSetAttribute(mma_gemm16<2, 32, 0>, cudaFuncAttributeMaxDynamicSharedMemorySize, 2 * STG_A);
    cudaFuncSetAttribute(mma_gemm16<3, 32, 1>, cudaFuncAttributeMaxDynamicSharedMemorySize, 2 * STG_A);
    cudaFuncSetAttribute(mma_gemm16<5, 32, 0>, cudaFuncAttributeMaxDynamicSharedMemorySize, 2 * STG_A);
    cudaFuncSetAttribute(mma_gemm16<4, 2, 0>,  cudaFuncAttributeMaxDynamicSharedMemorySize, 2 * STG_A);
    cudaFuncSetAttribute(xdd_fused, cudaFuncAttributeMaxDynamicSharedMemorySize, 81920);

    dim3 thr(256);
    const int wn4 = (int)(WSZ / 4);

    // 1) xl mix -> fp16 hi/lo, x_raw passthrough
    xprep_kernel<<<(int)(MC / 4 / 256), thr>>>(
        (const float4*)x, (const float4*)xlst, miux, xlhi, xllo, (float4*)(out + MC));
    // 2) A weight transpose+pad
    tpad_h<<<(256 * CDIM + 255) / 256, thr>>>(Aw, Athi, CDIM, 160, 256);
    // 3) square-weight casts, z-batched
    {
        SplitBatch sb = { { Wk, Wv, Wr, Wo } };
        split4_kernel<<<dim3((wn4 + 255) / 256, 4), thr>>>(sb, Whi, wn4);
    }
    // 4) t1 = tanh(xl @ A)   — single-pass
    {
        GemmBatch gbat = {};
        gbat.s[0] = { xlhi, xllo, Athi, t1, nullptr };
        mma_gemm16<2, 32, 0><<<dim3(2, MROWS / 128, 1), thr, 2 * STG_A>>>(gbat, CDIM, nullptr, nullptr);
    }

    // 5-6) decay-LoRA weight preps
    tpad_h<<<(128 * CDIM + 255) / 256, thr>>>(tdA, tdAthi, CDIM, 64, 128);
    tpad_h<<<(CDIM * 64 + 255) / 256, thr>>>(tdB, tdBthi, 64, CDIM, CDIM);

    // 7) fused xdd (k/v/r hi only)
    xdd_fused<<<dim3(CDIM / 64, MROWS / 64), thr, 81920>>>(
        t1, Blo5, x, xlst, lam, w0hi, w0lo, g0hi, g0lo, khi, vhi, rhi);

    // 8) h1 = tanh(w0 @ td_A) — single-pass
    {
        GemmBatch gbat = {};
        gbat.s[0] = { w0hi, w0lo, tdAthi, nullptr, nullptr };
        mma_gemm16<5, 32, 0><<<dim3(1, MROWS / 128, 1), thr, 2 * STG_A>>>(gbat, CDIM, h1hi, h1lo);
    }
    // 9) w = tdm + h1 @ td_B ; dec = exp(-exp(w)) — single-pass
    {
        GemmBatch gbat = {};
        gbat.s[0] = { h1hi, h1lo, tdBthi, w, tdm };
        mma_gemm16<4, 2, 0><<<dim3(CDIM / 128, MROWS / 128, 1), thr, 2 * STG_A>>>(gbat, 64, (__half*)dec, nullptr);
    }

    // 10) k/v/r projections, z-batched — single-pass
    {
        GemmBatch gbat = {};
        gbat.s[0] = { khi, khi, Whi + 0 * WSZ, kb, w };
        gbat.s[1] = { vhi, vhi, Whi + 1 * WSZ, vb, nullptr };
        gbat.s[2] = { rhi, rhi, Whi + 2 * WSZ, rb, nullptr };
        mma_gemm16<0, 32, 0><<<dim3(CDIM / 128, MROWS / 128, 3), thr, 2 * STG_A>>>(gbat, CDIM, nullptr, nullptr);
    }

    // 11-12) gate weight preps
    tpad_h<<<(256 * CDIM + 255) / 256, thr>>>(Wg1, G1thi, CDIM, 160, 256);
    tpad_h<<<(CDIM * 160 + 255) / 256, thr>>>(Wg2, G2thi, 160, CDIM, CDIM);

    // 13) g1 = tanh(g0 @ W_g1) -> fp16 hi/lo (2-pass: gate multiplies out)
    {
        GemmBatch gbat = {};
        gbat.s[0] = { g0hi, g0lo, G1thi, nullptr, nullptr };
        mma_gemm16<3, 32, 1><<<dim3(2, MROWS / 128, 1), thr, 2 * STG_A>>>(gbat, CDIM, g1hi, g1lo);
    }
    // 14) g = g1 @ W_g2   (K=160, 2-pass)
    {
        GemmBatch gbat = {};
        gbat.s[0] = { g1hi, g1lo, G2thi, gb, nullptr };
        mma_gemm16<0, 5, 1><<<dim3(CDIM / 128, MROWS / 128, 1), thr, 2 * STG_A>>>(gbat, 160, nullptr, nullptr);
    }

    // 15) cvec precompute
    cvec_kernel<<<(MROWS * HNUM) / 8, thr>>>(rb, kb, u, cv);

    // 16) WKV-6 scan (PF=16 ring, 2 steps/barrier)
    wkv_kernel<<<BSZ * HNUM, thr>>>(rb, kb, vb, dec, cv, s_in, yb, out + 2 * MC);

    // 17) GroupNorm * g -> fp16 hi only
    gn_kernel<<<(MROWS * HNUM) / 8, thr>>>(yb, gb, gam, bet, yhi);

    // 18) out = (yn*g) @ Wo^T — single-pass
    {
        GemmBatch gbat = {};
        gbat.s[0] = { yhi, yhi, Whi + 3 * WSZ, out, nullptr };
        mma_gemm16<0, 32, 0><<<dim3(CDIM / 128, MROWS / 128, 1), thr, 2 * STG_A>>>(gbat, CDIM, nullptr, nullptr);
    }
}

// round 16
// speedup vs baseline: 1.4599x; 1.0612x over previous
#include <cuda_runtime.h>
#include <cuda_fp16.h>
#include <stdint.h>
#include <math.h>

#define MROWS 16384   // B*T = 8*2048
#define CDIM  1024
#define HNUM  16
#define DDIM  64
#define TSEQ  2048
#define BSZ   8

// ---------------- scratch (static device memory; no runtime allocation) ----------------
__device__ float g_t1 [(size_t)MROWS * 160];
__device__ __half g_xlhi[(size_t)MROWS * CDIM];
__device__ __half g_w0hi[(size_t)MROWS * CDIM];
__device__ __half g_g0hi[(size_t)MROWS * CDIM];
__device__ __half g_g1hi[(size_t)MROWS * 160];
__device__ __half g_h1hi[(size_t)MROWS * 64];
__device__ __half g_khi[(size_t)MROWS * CDIM];
__device__ __half g_vhi[(size_t)MROWS * CDIM];
__device__ __half g_rhi[(size_t)MROWS * CDIM];
__device__ __half g_yhi[(size_t)MROWS * CDIM];
__device__ __half g_Whi[4][(size_t)CDIM * CDIM];
__device__ __half g_Athi[(size_t)256 * CDIM];
__device__ __half g_tdAthi[(size_t)128 * CDIM];
__device__ __half g_tdBthi[(size_t)CDIM * 64];
__device__ __half g_G1thi[(size_t)256 * CDIM];
__device__ __half g_G2thi[(size_t)CDIM * 160];
__device__ float g_w  [(size_t)MROWS * CDIM];
__device__ float g_dec[(size_t)MROWS * CDIM];
__device__ float g_kb [(size_t)MROWS * CDIM];
__device__ float g_vb [(size_t)MROWS * CDIM];
__device__ float g_rb [(size_t)MROWS * CDIM];
__device__ float g_gb [(size_t)MROWS * CDIM];
__device__ float g_yb [(size_t)MROWS * CDIM];
__device__ float g_cv [(size_t)MROWS * HNUM];

// ======================================================================================
// helpers
// ======================================================================================
__device__ __forceinline__ uint32_t smem_u32(const void* p) {
    uint32_t a;
    asm("{ .reg .u64 t; cvta.to.shared.u64 t, %1; cvt.u32.u64 %0, t; }" : "=r"(a) : "l"(p));
    return a;
}
__device__ __forceinline__ void ldsm4(uint32_t* r, uint32_t addr) {
    asm volatile("ldmatrix.sync.aligned.m8n8.x4.shared.b16 {%0,%1,%2,%3}, [%4];"
        : "=r"(r[0]), "=r"(r[1]), "=r"(r[2]), "=r"(r[3]) : "r"(addr));
}
__device__ __forceinline__ void mma16816(float* c, const uint32_t* a, const uint32_t* b) {
    asm volatile("mma.sync.aligned.m16n8k16.row.col.f32.f16.f16.f32 "
        "{%0,%1,%2,%3}, {%4,%5,%6,%7}, {%8,%9}, {%0,%1,%2,%3};"
        : "+f"(c[0]), "+f"(c[1]), "+f"(c[2]), "+f"(c[3])
        : "r"(a[0]), "r"(a[1]), "r"(a[2]), "r"(a[3]), "r"(b[0]), "r"(b[1]));
}
#define CP16(d, s) asm volatile("cp.async.cg.shared.global [%0], [%1], 16;" :: "r"(d), "l"(s))
#define CP4(d, s)  asm volatile("cp.async.ca.shared.global [%0], [%1], 4;"  :: "r"(d), "l"(s))
#define CPCOMMIT() asm volatile("cp.async.commit_group;" ::: "memory")
#define CPWAIT1()  asm volatile("cp.async.wait_group 1;" ::: "memory")
#define CPWAIT5()  asm volatile("cp.async.wait_group 5;" ::: "memory")

__device__ __forceinline__ uint2 cvt_hi4(float4 v) {
    __half2 H01 = __halves2half2(__float2half_rn(v.x), __float2half_rn(v.y));
    __half2 H23 = __halves2half2(__float2half_rn(v.z), __float2half_rn(v.w));
    return make_uint2(*(uint32_t*)&H01, *(uint32_t*)&H23);
}

// ======================================================================================
// prep kernels
// ======================================================================================
struct SplitBatch { const float* src[4]; };

__global__ void __launch_bounds__(256) split4_kernel(
    SplitBatch sb, __half* __restrict__ hi, int n4)
{
    int idx = blockIdx.x * 256 + threadIdx.x;
    if (idx >= n4) return;
    const size_t zoff = (size_t)blockIdx.y * CDIM * CDIM;
    *(uint2*)(hi + zoff + (size_t)idx * 4) = cvt_hi4(((const float4*)sb.src[blockIdx.y])[idx]);
}

__global__ void __launch_bounds__(256) tpad_h(
    const float* __restrict__ in, __half* __restrict__ ohi, int K, int N, int Npad)
{
    int t = blockIdx.x * 256 + threadIdx.x;
    if (t >= Npad * K) return;
    int n = t / K, k = t - n * K;
    float v = (n < N) ? in[(size_t)k * N + n] : 0.f;
    ohi[t] = __float2half_rn(v);
}

__global__ void __launch_bounds__(256) xprep_kernel(
    const float4* __restrict__ x, const float4* __restrict__ xl,
    const float* __restrict__ miux,
    __half* __restrict__ xhi, float4* __restrict__ xraw)
{
    int idx = blockIdx.x * 256 + threadIdx.x;   // MC/4 total
    float4 xv = x[idx], xlv = xl[idx];
    float4 mv = *(const float4*)(miux + (idx & 255) * 4);
    float4 o;
    o.x = fmaf(xlv.x - xv.x, mv.x, xv.x);
    o.y = fmaf(xlv.y - xv.y, mv.y, xv.y);
    o.z = fmaf(xlv.z - xv.z, mv.z, xv.z);
    o.w = fmaf(xlv.w - xv.w, mv.w, xv.w);
    *(uint2*)(xhi + (size_t)idx * 4) = cvt_hi4(o);
    xraw[idx] = xv;
}

// ======================================================================================
// fp16 HMMA GEMM (single A pass): C[m,n] = sum_k Ahi[m,k] * Bhi[n,k]
// Tile 128x128, BK=32, KCH chunks, stride kst, 2-stage cp.async, f32 acc.
// EPI 0: fp32 stride CDIM (+exp(min(w,0)) if wptr); 2: tanh fp32 s160;
// 3: tanh fp16 hi s160; 5: tanh fp16 hi s64; 4: +wptr[n], fp32 + exp(-exp())
// ======================================================================================
#define STG_A 20480
#define OBH3  10240

struct GemmSet {
    const __half *ahi, *bhi;
    float* c;
    const float* wptr;
};
struct GemmBatch { GemmSet s[3]; };

template <int EPI, int KCH>
__global__ void __launch_bounds__(256, 2) mma_gemm16(
    GemmBatch gbat, int kst, __half* __restrict__ chi)
{
    const GemmSet gs = gbat.s[blockIdx.z];
    extern __shared__ char smem[];
    const int tid = threadIdx.x, wid = tid >> 5, lane = tid & 31;
    const int bm = blockIdx.y, bn = blockIdx.x;
    const uint32_t sbase = smem_u32(smem);

    const int row = tid >> 1, half = tid & 1;
    const __half* pAhi = gs.ahi + (size_t)(bm * 128 + row) * kst + half * 16;
    const __half* pBhi = gs.bhi + (size_t)(bn * 128 + row) * kst + half * 16;
    const uint32_t dA = (uint32_t)(row * 80 + half * 32);

    auto issue = [&](int s, int k0) {
        uint32_t sb2 = sbase + s * STG_A;
        CP16(sb2 + dA,        pAhi + k0); CP16(sb2 + dA + 16,        pAhi + k0 + 8);
        CP16(sb2 + OBH3 + dA, pBhi + k0); CP16(sb2 + OBH3 + dA + 16, pBhi + k0 + 8);
    };

    float acc[2][8][4];
#pragma unroll
    for (int a = 0; a < 2; a++)
#pragma unroll
        for (int b = 0; b < 8; b++)
#pragma unroll
            for (int c = 0; c < 4; c++) acc[a][b][c] = 0.f;

    const int arow = (wid & 3) * 32 + (lane & 7) + ((lane >> 3) & 1) * 8;
    const int acol8 = (lane >> 4) * 8;
    const int brow = (wid >> 2) * 64 + ((lane >> 4) << 3) + (lane & 7);
    const int bcol8 = ((lane >> 3) & 1) * 8;

    issue(0, 0);  CPCOMMIT();
    if (KCH > 1) issue(1, 32);
    CPCOMMIT();

    for (int c = 0; c < KCH; c++) {
        CPWAIT1();
        __syncthreads();
        const uint32_t sA = sbase + (c & 1) * STG_A;
#pragma unroll
        for (int ks = 0; ks < 2; ks++) {
            const int kc = ks * 16;
            uint32_t ah[2][4], bh[4][4];
#pragma unroll
            for (int mt = 0; mt < 2; mt++) {
                uint32_t off = (uint32_t)((arow + mt * 16) * 40 + kc + acol8) * 2;
                ldsm4(ah[mt], sA + off);
            }
#pragma unroll
            for (int nt2 = 0; nt2 < 4; nt2++) {
                uint32_t boff = (uint32_t)((brow + nt2 * 16) * 40 + kc + bcol8) * 2;
                ldsm4(bh[nt2], sA + OBH3 + boff);
            }
#pragma unroll
            for (int nt2 = 0; nt2 < 4; nt2++)
#pragma unroll
                for (int mt = 0; mt < 2; mt++) {
                    mma16816(acc[mt][nt2 * 2],     ah[mt], bh[nt2]);
                    mma16816(acc[mt][nt2 * 2 + 1], ah[mt], bh[nt2] + 2);
                }
        }
        __syncthreads();
        {
            int cn = c + 2;
            if (cn < KCH) issue(cn & 1, cn * 32);
            CPCOMMIT();
        }
    }

    // epilogue
#pragma unroll
    for (int mt = 0; mt < 2; mt++) {
        const int m = bm * 128 + (wid & 3) * 32 + mt * 16 + (lane >> 2);
#pragma unroll
        for (int nt = 0; nt < 8; nt++) {
            const int n = bn * 128 + (wid >> 2) * 64 + nt * 8 + (lane & 3) * 2;
            float c0 = acc[mt][nt][0], c1 = acc[mt][nt][1];
            float c2 = acc[mt][nt][2], c3 = acc[mt][nt][3];
            if (EPI == 0) {
                size_t i0 = (size_t)m * CDIM + n;
                size_t i1 = i0 + (size_t)8 * CDIM;
                if (gs.wptr) {
                    float2 wa = *(const float2*)(gs.wptr + i0);
                    float2 wb = *(const float2*)(gs.wptr + i1);
                    c0 *= __expf(fminf(wa.x, 0.f)); c1 *= __expf(fminf(wa.y, 0.f));
                    c2 *= __expf(fminf(wb.x, 0.f)); c3 *= __expf(fminf(wb.y, 0.f));
                }
                *(float2*)(gs.c + i0) = make_float2(c0, c1);
                *(float2*)(gs.c + i1) = make_float2(c2, c3);
            } else if (EPI == 4) {
                size_t i0 = (size_t)m * CDIM + n;
                size_t i1 = i0 + (size_t)8 * CDIM;
                c0 += gs.wptr[n];     c1 += gs.wptr[n + 1];
                c2 += gs.wptr[n];     c3 += gs.wptr[n + 1];
                float* dec = (float*)chi;
                *(float2*)(gs.c + i0) = make_float2(c0, c1);
                *(float2*)(gs.c + i1) = make_float2(c2, c3);
                *(float2*)(dec + i0) = make_float2(__expf(-__expf(c0)), __expf(-__expf(c1)));
                *(float2*)(dec + i1) = make_float2(__expf(-__expf(c2)), __expf(-__expf(c3)));
            } else {
                const int NS = (EPI == 5) ? 64 : 160;
                if (n >= NS) continue;
                c0 = tanhf(c0); c1 = tanhf(c1); c2 = tanhf(c2); c3 = tanhf(c3);
                size_t i0 = (size_t)m * NS + n;
                size_t i1 = i0 + (size_t)8 * NS;
                if (EPI == 2) {
                    *(float2*)(gs.c + i0) = make_float2(c0, c1);
                    *(float2*)(gs.c + i1) = make_float2(c2, c3);
                } else {
                    __half2 H01 = __halves2half2(__float2half_rn(c0), __float2half_rn(c1));
                    __half2 H23 = __halves2half2(__float2half_rn(c2), __float2half_rn(c3));
                    *(uint32_t*)(chi + i0) = *(uint32_t*)&H01;
                    *(uint32_t*)(chi + i1) = *(uint32_t*)&H23;
                }
            }
        }
    }
}

// ======================================================================================
// fused xdd (K=32 LoRA): all 5 outputs -> fp16 hi only
// ======================================================================================
__global__ void __launch_bounds__(256) xdd_fused(
    const float* __restrict__ t1, const float* __restrict__ Blo5,
    const float* __restrict__ x, const float* __restrict__ xl,
    const float* __restrict__ lam,
    __half* __restrict__ w0hi, __half* __restrict__ g0hi,
    __half* __restrict__ khi, __half* __restrict__ vhi, __half* __restrict__ rhi)
{
    extern __shared__ float sh[];
    float* T1 = sh;              // [5][64][32]
    float* BL = sh + 10240;      // [5][32][64]
    const int tid = threadIdx.x;
    const int bm = blockIdx.y, bn = blockIdx.x;
    const int tx = tid & 15, ty = tid >> 4;

#pragma unroll
    for (int ii = 0; ii < 10; ii++) {
        int c4 = tid + ii * 256;
        int f = c4 >> 9, rem = c4 & 511;
        int row = rem >> 3, kq = rem & 7;
        float4 v = *(const float4*)(t1 + (size_t)f * MROWS * 32 + (size_t)(bm * 64 + row) * 32 + kq * 4);
        *(float4*)&T1[(f * 64 + row) * 32 + kq * 4] = v;
    }
#pragma unroll
    for (int ii = 0; ii < 10; ii++) {
        int c4 = tid + ii * 256;
        int f = c4 >> 9, rem = c4 & 511;
        int k = rem >> 4, cq = rem & 15;
        float4 v = *(const float4*)(Blo5 + (size_t)f * 32 * CDIM + (size_t)k * CDIM + bn * 64 + cq * 4);
        *(float4*)&BL[(f * 32 + k) * 64 + cq * 4] = v;
    }
    __syncthreads();

    float acc[5][4][4];
#pragma unroll
    for (int f = 0; f < 5; f++)
#pragma unroll
        for (int i = 0; i < 4; i++)
#pragma unroll
            for (int j = 0; j < 4; j++) acc[f][i][j] = 0.f;

    for (int k = 0; k < 32; k++) {
#pragma unroll
        for (int f = 0; f < 5; f++) {
            float4 b = *(const float4*)&BL[(f * 32 + k) * 64 + tx * 4];
            float a0 = T1[(f * 64 + ty * 4 + 0) * 32 + k];
            float a1 = T1[(f * 64 + ty * 4 + 1) * 32 + k];
            float a2 = T1[(f * 64 + ty * 4 + 2) * 32 + k];
            float a3 = T1[(f * 64 + ty * 4 + 3) * 32 + k];
            acc[f][0][0] = fmaf(a0, b.x, acc[f][0][0]); acc[f][0][1] = fmaf(a0, b.y, acc[f][0][1]);
            acc[f][0][2] = fmaf(a0, b.z, acc[f][0][2]); acc[f][0][3] = fmaf(a0, b.w, acc[f][0][3]);
            acc[f][1][0] = fmaf(a1, b.x, acc[f][1][0]); acc[f][1][1] = fmaf(a1, b.y, acc[f][1][1]);
            acc[f][1][2] = fmaf(a1, b.z, acc[f][1][2]); acc[f][1][3] = fmaf(a1, b.w, acc[f][1][3]);
            acc[f][2][0] = fmaf(a2, b.x, acc[f][2][0]); acc[f][2][1] = fmaf(a2, b.y, acc[f][2][1]);
            acc[f][2][2] = fmaf(a2, b.z, acc[f][2][2]); acc[f][2][3] = fmaf(a2, b.w, acc[f][2][3]);
            acc[f][3][0] = fmaf(a3, b.x, acc[f][3][0]); acc[f][3][1] = fmaf(a3, b.y, acc[f][3][1]);
            acc[f][3][2] = fmaf(a3, b.z, acc[f][3][2]); acc[f][3][3] = fmaf(a3, b.w, acc[f][3][3]);
        }
    }

    const int n0 = bn * 64 + tx * 4;
    float4 lamv[5];
#pragma unroll
    for (int f = 0; f < 5; f++) lamv[f] = *(const float4*)(lam + f * CDIM + n0);

#pragma unroll
    for (int i = 0; i < 4; i++) {
        const int m = bm * 64 + ty * 4 + i;
        size_t ix = (size_t)m * CDIM + n0;
        float4 xv = *(const float4*)(x + ix);
        float4 xlv = *(const float4*)(xl + ix);
        float4 ba = make_float4(xlv.x - xv.x, xlv.y - xv.y, xlv.z - xv.z, xlv.w - xv.w);
        float4 o[5];
#pragma unroll
        for (int f = 0; f < 5; f++) {
            o[f].x = fmaf(ba.x, lamv[f].x + acc[f][i][0], xv.x);
            o[f].y = fmaf(ba.y, lamv[f].y + acc[f][i][1], xv.y);
            o[f].z = fmaf(ba.z, lamv[f].z + acc[f][i][2], xv.z);
            o[f].w = fmaf(ba.w, lamv[f].w + acc[f][i][3], xv.w);
        }
        *(uint2*)(w0hi + ix) = cvt_hi4(o[0]);
        *(uint2*)(khi + ix)  = cvt_hi4(o[1]);
        *(uint2*)(vhi + ix)  = cvt_hi4(o[2]);
        *(uint2*)(rhi + ix)  = cvt_hi4(o[3]);
        *(uint2*)(g0hi + ix) = cvt_hi4(o[4]);
    }
}

// ======================================================================================
// cvec[m,h] = sum_j r*u*k
// ======================================================================================
__global__ void __launch_bounds__(256) cvec_kernel(
    const float* __restrict__ rb, const float* __restrict__ kb,
    const float* __restrict__ u, float* __restrict__ cv)
{
    int gw = (blockIdx.x * 256 + threadIdx.x) >> 5;
    int lane = threadIdx.x & 31;
    int m = gw >> 4, h = gw & 15;
    size_t base = (size_t)m * CDIM + h * DDIM;
    float p = rb[base + lane] * u[h * DDIM + lane] * kb[base + lane]
            + rb[base + 32 + lane] * u[h * DDIM + 32 + lane] * kb[base + 32 + lane];
#pragma unroll
    for (int o = 16; o > 0; o >>= 1) p += __shfl_xor_sync(0xffffffffu, p, o);
    if (lane == 0) cv[(size_t)m * HNUM + h] = p;
}

// ======================================================================================
// WKV-6 scan — 256 threads, PF=16 cp.async ring, TWO steps per barrier
// ======================================================================================
#define PF 16
__global__ void __launch_bounds__(256) wkv_kernel(
    const float* __restrict__ r, const float* __restrict__ k,
    const float* __restrict__ v, const float* __restrict__ dec,
    const float* __restrict__ cv, const float* __restrict__ s_in,
    float* __restrict__ y, float* __restrict__ s_out)
{
    const int bh = blockIdx.x;
    const int b = bh >> 4, h = bh & 15;
    const int tid = threadIdx.x;
    const int i  = tid & 63;
    const int jg = tid >> 6;
    const int j0 = jg * 16;

    __shared__ float buf[PF][4][64];
    __shared__ float cb[PF];
    __shared__ float ypart[2][2][4][64];

    float st[16];
    size_t sbase = (((size_t)b * HNUM + h) * DDIM + j0) * DDIM + i;
#pragma unroll
    for (int q = 0; q < 16; q++) st[q] = s_in[sbase + (size_t)q * DDIM];

    const int arr = tid >> 6, idx = tid & 63;
    const float* lp = (arr == 0) ? r : (arr == 1) ? k : (arr == 2) ? v : dec;
    const size_t base0 = ((size_t)b * TSEQ) * CDIM + h * DDIM;
    const size_t cvbase = (size_t)(b * TSEQ) * HNUM + h;

    const uint32_t sbuf = smem_u32(&buf[0][0][0]);
    const uint32_t scb  = smem_u32(&cb[0]);
    const uint32_t mydst = (uint32_t)((arr * 64 + idx) * 4);

    for (int p = 0; p < 7; p++) {
        CP4(sbuf + (uint32_t)((2 * p) * 1024) + mydst,     lp + base0 + (size_t)(2 * p) * CDIM + idx);
        CP4(sbuf + (uint32_t)((2 * p + 1) * 1024) + mydst, lp + base0 + (size_t)(2 * p + 1) * CDIM + idx);
        if (tid == 0) {
            CP4(scb + (2 * p) * 4,     cv + cvbase + (size_t)(2 * p) * HNUM);
            CP4(scb + (2 * p + 1) * 4, cv + cvbase + (size_t)(2 * p + 1) * HNUM);
        }
        CPCOMMIT();
    }
    CPWAIT5();
    __syncthreads();

    for (int t = 0; t < TSEQ; t += 2) {
        const int it = (t >> 1) & 1;
        const int sl0 = t & (PF - 1), sl1 = (t + 1) & (PF - 1);

        {
            const float vi = buf[sl0][2][i];
            float acc = 0.f;
#pragma unroll
            for (int q = 0; q < 16; q += 4) {
                float4 r4 = *(const float4*)&buf[sl0][0][j0 + q];
                float4 k4 = *(const float4*)&buf[sl0][1][j0 + q];
                float4 d4 = *(const float4*)&buf[sl0][3][j0 + q];
                acc = fmaf(r4.x, st[q + 0], acc); st[q + 0] = fmaf(d4.x, st[q + 0], k4.x * vi);
                acc = fmaf(r4.y, st[q + 1], acc); st[q + 1] = fmaf(d4.y, st[q + 1], k4.y * vi);
                acc = fmaf(r4.z, st[q + 2], acc); st[q + 2] = fmaf(d4.z, st[q + 2], k4.z * vi);
                acc = fmaf(r4.w, st[q + 3], acc); st[q + 3] = fmaf(d4.w, st[q + 3], k4.w * vi);
            }
            ypart[it][0][jg][i] = acc;
        }
        {
            const float vi = buf[sl1][2][i];
            float acc = 0.f;
#pragma unroll
            for (int q = 0; q < 16; q += 4) {
                float4 r4 = *(const float4*)&buf[sl1][0][j0 + q];
                float4 k4 = *(const float4*)&buf[sl1][1][j0 + q];
                float4 d4 = *(const float4*)&buf[sl1][3][j0 + q];
                acc = fmaf(r4.x, st[q + 0], acc); st[q + 0] = fmaf(d4.x, st[q + 0], k4.x * vi);
                acc = fmaf(r4.y, st[q + 1], acc); st[q + 1] = fmaf(d4.y, st[q + 1], k4.y * vi);
                acc = fmaf(r4.z, st[q + 2], acc); st[q + 2] = fmaf(d4.z, st[q + 2], k4.z * vi);
                acc = fmaf(r4.w, st[q + 3], acc); st[q + 3] = fmaf(d4.w, st[q + 3], k4.w * vi);
            }
            ypart[it][1][jg][i] = acc;
        }

        float vA = 0.f, cA = 0.f, vB = 0.f, cB = 0.f;
        if (tid < 64) {
            vA = buf[sl0][2][tid]; cA = cb[sl0];
            vB = buf[sl1][2][tid]; cB = cb[sl1];
        }

        {
            int t0 = t + 14, t1 = t + 15;
            if (t0 < TSEQ) {
                CP4(sbuf + (uint32_t)((t0 & (PF - 1)) * 1024) + mydst, lp + base0 + (size_t)t0 * CDIM + idx);
                if (tid == 0) CP4(scb + (t0 & (PF - 1)) * 4, cv + cvbase + (size_t)t0 * HNUM);
            }
            if (t1 < TSEQ) {
                CP4(sbuf + (uint32_t)((t1 & (PF - 1)) * 1024) + mydst, lp + base0 + (size_t)t1 * CDIM + idx);
                if (tid == 0) CP4(scb + (t1 & (PF - 1)) * 4, cv + cvbase + (size_t)t1 * HNUM);
            }
            CPCOMMIT();
        }
        CPWAIT5();
        __syncthreads();

        if (tid < 64) {
            float yA = ypart[it][0][0][tid] + ypart[it][0][1][tid]
                     + ypart[it][0][2][tid] + ypart[it][0][3][tid] + vA * cA;
            float yB = ypart[it][1][0][tid] + ypart[it][1][1][tid]
                     + ypart[it][1][2][tid] + ypart[it][1][3][tid] + vB * cB;
            y[base0 + (size_t)t * CDIM + tid] = yA;
            y[base0 + (size_t)(t + 1) * CDIM + tid] = yB;
        }
    }

#pragma unroll
    for (int q = 0; q < 16; q++) s_out[sbase + (size_t)q * DDIM] = st[q];
}

// ======================================================================================
// GroupNorm * g -> fp16 hi only
// ======================================================================================
__global__ void __launch_bounds__(256) gn_kernel(
    const float* __restrict__ y, const float* __restrict__ g,
    const float* __restrict__ gamma, const float* __restrict__ beta,
    __half* __restrict__ yhi)
{
    int warp = (blockIdx.x * blockDim.x + threadIdx.x) >> 5;
    int lane = threadIdx.x & 31;
    int m = warp >> 4, h = warp & 15;
    size_t base = (size_t)m * CDIM + h * DDIM;

    float2 vv = *(const float2*)&y[base + lane * 2];
    float s  = vv.x + vv.y;
    float sq = vv.x * vv.x + vv.y * vv.y;
#pragma unroll
    for (int o = 16; o > 0; o >>= 1) {
        s  += __shfl_xor_sync(0xffffffffu, s,  o);
        sq += __shfl_xor_sync(0xffffffffu, sq, o);
    }
    float mean = s * (1.f / 64.f);
    float var  = sq * (1.f / 64.f) - mean * mean;
    float inv  = rsqrtf(var + 1e-5f * (float)HNUM);

    int c0 = h * DDIM + lane * 2;
    float2 gv = *(const float2*)&g[base + lane * 2];
    float o0 = ((vv.x - mean) * inv * gamma[c0]     + beta[c0])     * gv.x;
    float o1 = ((vv.y - mean) * inv * gamma[c0 + 1] + beta[c0 + 1]) * gv.y;

    __half2 H = __halves2half2(__float2half_rn(o0), __float2half_rn(o1));
    *(uint32_t*)(yhi + base + lane * 2) = *(uint32_t*)&H;
}

// ======================================================================================
extern "C" void kernel_launch(void* const* d_in, const int* in_sizes, int n_in,
                              void* d_out, int out_size)
{
    const float* x    = (const float*)d_in[0];
    const float* xlst = (const float*)d_in[1];
    const float* s_in = (const float*)d_in[2];
    const float* miux = (const float*)d_in[3];
    const float* lam  = (const float*)d_in[4];
    const float* Aw   = (const float*)d_in[5];
    const float* Blo5 = (const float*)d_in[6];
    const float* tdm  = (const float*)d_in[7];
    const float* tdA  = (const float*)d_in[8];
    const float* tdB  = (const float*)d_in[9];
    const float* u    = (const float*)d_in[10];
    const float* Wk   = (const float*)d_in[11];
    const float* Wv   = (const float*)d_in[12];
    const float* Wr   = (const float*)d_in[13];
    const float* Wo   = (const float*)d_in[14];
    const float* Wg1  = (const float*)d_in[15];
    const float* Wg2  = (const float*)d_in[16];
    const float* gam  = (const float*)d_in[17];
    const float* bet  = (const float*)d_in[18];
    float* out = (float*)d_out;

    float *t1, *w, *dec, *kb, *vb, *rb, *gb, *yb, *cv;
    __half *xlhi, *w0hi, *g0hi, *g1hi, *h1hi;
    __half *khi, *vhi, *rhi, *yhi, *Whi;
    __half *Athi, *tdAthi, *tdBthi, *G1thi, *G2thi;
    cudaGetSymbolAddress((void**)&t1,  g_t1);
    cudaGetSymbolAddress((void**)&xlhi, g_xlhi);
    cudaGetSymbolAddress((void**)&w0hi, g_w0hi);
    cudaGetSymbolAddress((void**)&g0hi, g_g0hi);
    cudaGetSymbolAddress((void**)&g1hi, g_g1hi);
    cudaGetSymbolAddress((void**)&h1hi, g_h1hi);
    cudaGetSymbolAddress((void**)&khi, g_khi);
    cudaGetSymbolAddress((void**)&vhi, g_vhi);
    cudaGetSymbolAddress((void**)&rhi, g_rhi);
    cudaGetSymbolAddress((void**)&yhi, g_yhi);
    cudaGetSymbolAddress((void**)&Whi, g_Whi);
    cudaGetSymbolAddress((void**)&Athi, g_Athi);
    cudaGetSymbolAddress((void**)&tdAthi, g_tdAthi);
    cudaGetSymbolAddress((void**)&tdBthi, g_tdBthi);
    cudaGetSymbolAddress((void**)&G1thi, g_G1thi);
    cudaGetSymbolAddress((void**)&G2thi, g_G2thi);
    cudaGetSymbolAddress((void**)&w,   g_w);
    cudaGetSymbolAddress((void**)&dec, g_dec);
    cudaGetSymbolAddress((void**)&kb,  g_kb);
    cudaGetSymbolAddress((void**)&vb,  g_vb);
    cudaGetSymbolAddress((void**)&rb,  g_rb);
    cudaGetSymbolAddress((void**)&gb,  g_gb);
    cudaGetSymbolAddress((void**)&yb,  g_yb);
    cudaGetSymbolAddress((void**)&cv,  g_cv);

    const size_t WSZ = (size_t)CDIM * CDIM;
    const size_t MC = (size_t)MROWS * CDIM;
    cudaFuncSetAttribute(mma_gemm16<0, 32>, cudaFuncAttributeMaxDynamicSharedMemorySize, 2 * STG_A);
    cudaFuncSetAttribute(mma_gemm16<0, 5>,  cudaFuncAttributeMaxDynamicSharedMemorySize, 2 * STG_A);
    cudaFuncSetAttribute(mma_gemm16<2, 32>, cudaFuncAttributeMaxDynamicSharedMemorySize, 2 * STG_A);
    cudaFuncSetAttribute(mma_gemm16<3, 32>, cudaFuncAttributeMaxDynamicSharedMemorySize, 2 * STG_A);
    cudaFuncSetAttribute(mma_gemm16<5, 32>, cudaFuncAttributeMaxDynamicSharedMemorySize, 2 * STG_A);
    cudaFuncSetAttribute(mma_gemm16<4, 2>,  cudaFuncAttributeMaxDynamicSharedMemorySize, 2 * STG_A);
    cudaFuncSetAttribute(xdd_fused, cudaFuncAttributeMaxDynamicSharedMemorySize, 81920);

    dim3 thr(256);
    const int wn4 = (int)(WSZ / 4);

    // 1) xl mix -> fp16 hi, x_raw passthrough
    xprep_kernel<<<(int)(MC / 4 / 256), thr>>>(
        (const float4*)x, (const float4*)xlst, miux, xlhi, (float4*)(out + MC));
    // 2) A weight transpose+pad
    tpad_h<<<(256 * CDIM + 255) / 256, thr>>>(Aw, Athi, CDIM, 160, 256);
    // 3) square-weight casts, z-batched
    {
        SplitBatch sb = { { Wk, Wv, Wr, Wo } };
        split4_kernel<<<dim3((wn4 + 255) / 256, 4), thr>>>(sb, Whi, wn4);
    }
    // 4) t1 = tanh(xl @ A)   — single-pass
    {
        GemmBatch gbat = {};
        gbat.s[0] = { xlhi, Athi, t1, nullptr };
        mma_gemm16<2, 32><<<dim3(2, MROWS / 128, 1), thr, 2 * STG_A>>>(gbat, CDIM, nullptr);
    }

    // 5-6) decay-LoRA weight preps
    tpad_h<<<(128 * CDIM + 255) / 256, thr>>>(tdA, tdAthi, CDIM, 64, 128);
    tpad_h<<<(CDIM * 64 + 255) / 256, thr>>>(tdB, tdBthi, 64, CDIM, CDIM);

    // 7) fused xdd (all hi only)
    xdd_fused<<<dim3(CDIM / 64, MROWS / 64), thr, 81920>>>(
        t1, Blo5, x, xlst, lam, w0hi, g0hi, khi, vhi, rhi);

    // 8) h1 = tanh(w0 @ td_A) — single-pass
    {
        GemmBatch gbat = {};
        gbat.s[0] = { w0hi, tdAthi, nullptr, nullptr };
        mma_gemm16<5, 32><<<dim3(1, MROWS / 128, 1), thr, 2 * STG_A>>>(gbat, CDIM, h1hi);
    }
    // 9) w = tdm + h1 @ td_B ; dec = exp(-exp(w)) — single-pass
    {
        GemmBatch gbat = {};
        gbat.s[0] = { h1hi, tdBthi, w, tdm };
        mma_gemm16<4, 2><<<dim3(CDIM / 128, MROWS / 128, 1), thr, 2 * STG_A>>>(gbat, 64, (__half*)dec);
    }

    // 10) k/v/r projections, z-batched — single-pass
    {
        GemmBatch gbat = {};
        gbat.s[0] = { khi, Whi + 0 * WSZ, kb, w };
        gbat.s[1] = { vhi, Whi + 1 * WSZ, vb, nullptr };
        gbat.s[2] = { rhi, Whi + 2 * WSZ, rb, nullptr };
        mma_gemm16<0, 32><<<dim3(CDIM / 128, MROWS / 128, 3), thr, 2 * STG_A>>>(gbat, CDIM, nullptr);
    }

    // 11-12) gate weight preps
    tpad_h<<<(256 * CDIM + 255) / 256, thr>>>(Wg1, G1thi, CDIM, 160, 256);
    tpad_h<<<(CDIM * 160 + 255) / 256, thr>>>(Wg2, G2thi, 160, CDIM, CDIM);

    // 13) g1 = tanh(g0 @ W_g1) -> fp16 hi — single-pass
    {
        GemmBatch gbat = {};
        gbat.s[0] = { g0hi, G1thi, nullptr, nullptr };
        mma_gemm16<3, 32><<<dim3(2, MROWS / 128, 1), thr, 2 * STG_A>>>(gbat, CDIM, g1hi);
    }
    // 14) g = g1 @ W_g2   (K=160) — single-pass
    {
        GemmBatch gbat = {};
        gbat.s[0] = { g1hi, G2thi, gb, nullptr };
        mma_gemm16<0, 5><<<dim3(CDIM / 128, MROWS / 128, 1), thr, 2 * STG_A>>>(gbat, 160, nullptr);
    }

    // 15) cvec precompute
    cvec_kernel<<<(MROWS * HNUM) / 8, thr>>>(rb, kb, u, cv);

    // 16) WKV-6 scan (PF=16 ring, 2 steps/barrier)
    wkv_kernel<<<BSZ * HNUM, thr>>>(rb, kb, vb, dec, cv, s_in, yb, out + 2 * MC);

    // 17) GroupNorm * g -> fp16 hi only
    gn_kernel<<<(MROWS * HNUM) / 8, thr>>>(yb, gb, gam, bet, yhi);

    // 18) out = (yn*g) @ Wo^T — single-pass
    {
        GemmBatch gbat = {};
        gbat.s[0] = { yhi, Whi + 3 * WSZ, out, nullptr };
        mma_gemm16<0, 32><<<dim3(CDIM / 128, MROWS / 128, 1), thr, 2 * STG_A>>>(gbat, CDIM, nullptr);
    }
}